// round 1
// baseline (speedup 1.0000x reference)
#include <cuda_runtime.h>
#include <math.h>

// Global accumulators for the two level sums (double for accuracy).
__device__ double g_sum[2];

__global__ void init_sums_kernel() {
    g_sum[0] = 0.0;
    g_sum[1] = 0.0;
}

// Fused Gram + batch-softmax + |diff| partial-sum kernel.
// One block computes a 64x64 (i,j) output tile for ALL 4 batches and BOTH
// tensors (8 "combos"), then does the batch-axis softmax + abs-diff epilogue
// and accumulates a weighted partial sum (upper-triangle symmetry: off-diag
// weight 2, diag weight 1, lower triangle skipped).
//
// Shared layout (dynamic):
//   As: 64 x 64 floats (A tile, c-major)            [16 KB]
//   Bs: 64 x 64 floats (B tile)                     [16 KB]
//   Cs: 8 combos x 16 elems x 256 threads floats    [128 KB]
__global__ void __launch_bounds__(256, 1)
gram_loss_kernel(const float* __restrict__ f1, const float* __restrict__ f2,
                 int C, int HW, int level)
{
    const int ti = blockIdx.y;
    const int tj = blockIdx.x;
    if (tj < ti) return;  // upper triangle only

    extern __shared__ float smem[];
    float* As = smem;            // 4096 floats
    float* Bs = smem + 4096;     // 4096 floats
    float* Cs = smem + 8192;     // 8*16*256 = 32768 floats

    const int tid = threadIdx.x;
    const int tx = tid & 15;     // j sub-tile (x4)
    const int ty = tid >> 4;     // i sub-tile (x4)
    const int i0 = ti * 64;
    const int j0 = tj * 64;

    // ---- main loop: 8 (tensor, batch) combos ----
    for (int t = 0; t < 2; ++t) {
        const float* fbase = t ? f2 : f1;
        for (int b = 0; b < 4; ++b) {
            const float* f = fbase + (size_t)b * C * HW;

            float acc[16];
#pragma unroll
            for (int k = 0; k < 16; ++k) acc[k] = 0.0f;

            for (int kc = 0; kc < C; kc += 64) {
                __syncthreads();  // protect prior tile reads
                // Load 64(c) x 64(pos) tiles of A (cols i0..) and B (cols j0..)
#pragma unroll
                for (int p = 0; p < 4; ++p) {
                    int v = p * 256 + tid;        // float4 index 0..1023
                    int row = v >> 4;             // c within chunk
                    int col = (v & 15) << 2;      // position offset
                    const float* gsrc = f + (size_t)(kc + row) * HW;
                    ((float4*)As)[v] = *(const float4*)(gsrc + i0 + col);
                    ((float4*)Bs)[v] = *(const float4*)(gsrc + j0 + col);
                }
                __syncthreads();

                const float4* As4 = (const float4*)As;
                const float4* Bs4 = (const float4*)Bs;
#pragma unroll 8
                for (int c = 0; c < 64; ++c) {
                    float4 a4 = As4[c * 16 + ty];
                    float4 b4 = Bs4[c * 16 + tx];
                    acc[0]  += a4.x * b4.x;
                    acc[1]  += a4.x * b4.y;
                    acc[2]  += a4.x * b4.z;
                    acc[3]  += a4.x * b4.w;
                    acc[4]  += a4.y * b4.x;
                    acc[5]  += a4.y * b4.y;
                    acc[6]  += a4.y * b4.z;
                    acc[7]  += a4.y * b4.w;
                    acc[8]  += a4.z * b4.x;
                    acc[9]  += a4.z * b4.y;
                    acc[10] += a4.z * b4.z;
                    acc[11] += a4.z * b4.w;
                    acc[12] += a4.w * b4.x;
                    acc[13] += a4.w * b4.y;
                    acc[14] += a4.w * b4.z;
                    acc[15] += a4.w * b4.w;
                }
            }

            // Stash this combo's 16 results (combo = t*4 + b).
            float* cdst = Cs + (t * 4 + b) * (16 * 256);
#pragma unroll
            for (int k = 0; k < 16; ++k) cdst[k * 256 + tid] = acc[k];
        }
    }
    __syncthreads();  // all combos stashed

    // ---- epilogue: batch softmax + |diff|, weighted by symmetry ----
    float wsum = 0.0f;
#pragma unroll
    for (int k = 0; k < 16; ++k) {
        const int di = k >> 2, dj = k & 3;
        const int i = i0 + ty * 4 + di;
        const int j = j0 + tx * 4 + dj;
        float w;
        if (ti < tj)      w = 2.0f;
        else if (j > i)   w = 2.0f;
        else if (j == i)  w = 1.0f;
        else              continue;  // lower triangle of diagonal tile

        float g1v[4], g2v[4];
#pragma unroll
        for (int b = 0; b < 4; ++b) {
            g1v[b] = Cs[b * 4096 + k * 256 + tid];
            g2v[b] = Cs[(4 + b) * 4096 + k * 256 + tid];
        }
        float m1 = fmaxf(fmaxf(g1v[0], g1v[1]), fmaxf(g1v[2], g1v[3]));
        float m2 = fmaxf(fmaxf(g2v[0], g2v[1]), fmaxf(g2v[2], g2v[3]));
        float e1[4], e2[4];
        float s1 = 0.0f, s2 = 0.0f;
#pragma unroll
        for (int b = 0; b < 4; ++b) {
            e1[b] = __expf(g1v[b] - m1); s1 += e1[b];
            e2[b] = __expf(g2v[b] - m2); s2 += e2[b];
        }
        const float inv1 = __frcp_rn(s1);
        const float inv2 = __frcp_rn(s2);
        float d = 0.0f;
#pragma unroll
        for (int b = 0; b < 4; ++b)
            d += fabsf(e1[b] * inv1 - e2[b] * inv2);
        wsum += w * d;
    }

    // ---- block reduction (reuse As) ----
    __syncthreads();
    As[tid] = wsum;
    __syncthreads();
    for (int s = 128; s > 0; s >>= 1) {
        if (tid < s) As[tid] += As[tid + s];
        __syncthreads();
    }
    if (tid == 0) atomicAdd(&g_sum[level], (double)As[0]);
}

__global__ void finalize_kernel(float* out) {
    const double n0 = 4.0 * 4096.0 * 4096.0;
    const double n1 = 4.0 * 1024.0 * 1024.0;
    out[0] = (float)((g_sum[0] / n0 + g_sum[1] / n1) * 0.5);
}

extern "C" void kernel_launch(void* const* d_in, const int* in_sizes, int n_in,
                              void* d_out, int out_size)
{
    const float* fea1_0 = (const float*)d_in[0];  // (4, 64, 64, 64)
    const float* fea1_1 = (const float*)d_in[1];  // (4, 128, 32, 32)
    const float* fea2_0 = (const float*)d_in[2];
    const float* fea2_1 = (const float*)d_in[3];
    float* out = (float*)d_out;

    const size_t smem_bytes = (4096 + 4096 + 8 * 16 * 256) * sizeof(float); // 160 KB
    cudaFuncSetAttribute(gram_loss_kernel,
                         cudaFuncAttributeMaxDynamicSharedMemorySize,
                         (int)smem_bytes);

    init_sums_kernel<<<1, 1>>>();

    // Level 0: C=64, HW=4096 -> 64x64 tiles of 64
    gram_loss_kernel<<<dim3(64, 64), 256, smem_bytes>>>(fea1_0, fea2_0, 64, 4096, 0);
    // Level 1: C=128, HW=1024 -> 16x16 tiles of 64
    gram_loss_kernel<<<dim3(16, 16), 256, smem_bytes>>>(fea1_1, fea2_1, 128, 1024, 1);

    finalize_kernel<<<1, 1>>>(out);
}

// round 3
// speedup vs baseline: 1.0919x; 1.0919x over previous
#include <cuda_runtime.h>
#include <cuda_bf16.h>
#include <cstdint>
#include <math.h>

// ============================================================================
// Globals
// ============================================================================

__device__ double g_sum[2];

// bf16 hi/lo panels, [tb = t*4+b][pos][c] layout (c contiguous):
//  L0 hi: off 0        size 2*4*4096*64 = 2097152
//  L0 lo: off 2097152  size 2097152
//  L1 hi: off 4194304  size 2*4*1024*128 = 1048576
//  L1 lo: off 5242880  size 1048576
#define L0_HI 0
#define L0_LO 2097152
#define L1_HI 4194304
#define L1_LO 5242880
__device__ __nv_bfloat16 g_scratch[6291456];

__global__ void init_sums_kernel() { g_sum[0] = 0.0; g_sum[1] = 0.0; }

// ============================================================================
// Pre-convert: fp32 [b][c][pos] -> bf16 hi & lo panels [tb][pos][C]
// ============================================================================
template <int C>
__global__ void __launch_bounds__(256)
convert_kernel(const float* __restrict__ f1, const float* __restrict__ f2,
               int HW, int hi_off, int lo_off)
{
    __shared__ float tile[C * 65];  // [c][pos0..63], padded
    const int t = blockIdx.z, b = blockIdx.y;
    const int pos0 = blockIdx.x * 64;
    const float* src = (t ? f2 : f1) + (size_t)b * C * HW;

    for (int idx = threadIdx.x; idx < C * 64; idx += 256) {
        int c = idx >> 6, p = idx & 63;
        tile[c * 65 + p] = src[(size_t)c * HW + pos0 + p];
    }
    __syncthreads();

    const size_t pb = ((size_t)(t * 4 + b) * HW + pos0) * C;
    __nv_bfloat16* oh = g_scratch + hi_off + pb;
    __nv_bfloat16* ol = g_scratch + lo_off + pb;
    constexpr int CSH = (C == 64) ? 6 : 7;
    for (int idx = threadIdx.x; idx < 64 * C; idx += 256) {
        int p = idx >> CSH, c = idx & (C - 1);
        float v = tile[c * 65 + p];
        __nv_bfloat16 hi = __float2bfloat16(v);
        oh[(size_t)p * C + c] = hi;
        ol[(size_t)p * C + c] = __float2bfloat16(v - __bfloat162float(hi));
    }
}

// ============================================================================
// mma.sync helpers (sm_80+ PTX -> works on plain sm_100 target)
// ============================================================================

__device__ __forceinline__ uint32_t smem_to_u32(const void* p) {
    uint32_t a;
    asm("{ .reg .u64 t; cvta.to.shared.u64 t, %1; cvt.u32.u64 %0, t; }"
        : "=r"(a) : "l"(p));
    return a;
}

__device__ __forceinline__ void ldmatrix_x4(uint32_t* r, uint32_t addr) {
    asm volatile(
        "ldmatrix.sync.aligned.m8n8.x4.shared.b16 {%0,%1,%2,%3}, [%4];"
        : "=r"(r[0]), "=r"(r[1]), "=r"(r[2]), "=r"(r[3]) : "r"(addr));
}

__device__ __forceinline__ void mma_16816(float* d, const uint32_t* a,
                                          const uint32_t* b) {
    asm volatile(
        "mma.sync.aligned.m16n8k16.row.col.f32.bf16.bf16.f32 "
        "{%0,%1,%2,%3}, {%4,%5,%6,%7}, {%8,%9}, {%0,%1,%2,%3};"
        : "+f"(d[0]), "+f"(d[1]), "+f"(d[2]), "+f"(d[3])
        : "r"(a[0]), "r"(a[1]), "r"(a[2]), "r"(a[3]), "r"(b[0]), "r"(b[1]));
}

// ============================================================================
// Fused Gram (mma.sync, 3-pass hi/lo) + batch-softmax + |diff| partial sum
// Block: 64x64 tile, 256 threads = 8 warps (4 row x 2 col), warp = 16m x 32n.
// smem: A_hi | A_lo | B_hi | B_lo tiles (SW128, 128B rows, k-blocked) + Cs stash.
// ============================================================================
template <int C>
__global__ void __launch_bounds__(256, 1)
gram_loss_mma(int HW, int hi_off, int lo_off, int level)
{
    const int ti = blockIdx.y, tj = blockIdx.x;
    if (tj < ti) return;  // upper triangle only

    constexpr int KB = C / 64;             // 8KB k-blocks per tile
    constexpr int TILE_B = KB * 8192;      // bytes per tile
    constexpr int NCH = C / 8;             // 16B chunks per row
    constexpr int KSTEPS = C / 16;

    extern __shared__ char smem[];
    const uint32_t sb = smem_to_u32(smem);
    float* Cs = (float*)(smem + 4 * TILE_B);   // [combo][slot 0..15][tid]

    const int tid = threadIdx.x;
    const int wid = tid >> 5, lid = tid & 31;
    const int wrow = wid & 3, wcol = wid >> 2;
    const int i0 = ti * 64, j0 = tj * 64;

    // ---- per-lane ldmatrix base addressing (lane-dependent, ks-invariant) ----
    const int mat = lid >> 3, lrow = lid & 7;
    // A matrices: mat0=(m0-7,kh0) m1=(m8-15,kh0) m2=(m0-7,kh1) m3=(m8-15,kh1)
    const int a_row = wrow * 16 + ((mat & 1) << 3) + lrow;
    const int a_kh = mat >> 1;
    // B matrices for n-pair p: mat0=(n0-7,kh0) m1=(n0-7,kh1) m2=(n8-15,kh0) m3=(n8-15,kh1)
    const int b_kh = mat & 1;
    const int b_row0 = wcol * 32 + ((mat >> 1) << 3) + lrow;       // pair 0
    const int b_row1 = b_row0 + 16;                                 // pair 1

    const uint32_t a_rb = sb + a_row * 128;
    const uint32_t b_rb0 = sb + 2 * TILE_B + b_row0 * 128;
    const uint32_t b_rb1 = sb + 2 * TILE_B + b_row1 * 128;
    const int a_r7 = a_row & 7, b_r70 = b_row0 & 7, b_r71 = b_row1 & 7;

    for (int combo = 0; combo < 8; ++combo) {
        __syncthreads();  // protect tiles from prior combo's readers

        // ---- load 4 tiles: A_hi, A_lo (rows i0..), B_hi, B_lo (rows j0..) ----
        {
            const size_t pbase = (size_t)combo * HW * C;
            const __nv_bfloat16* srcs[4] = {
                g_scratch + hi_off + pbase + (size_t)i0 * C,
                g_scratch + lo_off + pbase + (size_t)i0 * C,
                g_scratch + hi_off + pbase + (size_t)j0 * C,
                g_scratch + lo_off + pbase + (size_t)j0 * C };
            #pragma unroll
            for (int tile = 0; tile < 4; ++tile) {
                const __nv_bfloat16* s = srcs[tile];
                char* dst = smem + tile * TILE_B;
                for (int v = tid; v < 64 * NCH; v += 256) {
                    const int row = v / NCH, kcq = v % NCH;
                    const int kb = kcq >> 3, kc8 = kcq & 7;
                    float4 d = *(const float4*)(s + (size_t)row * C + kcq * 8);
                    *(float4*)(dst + kb * 8192 + row * 128 +
                               ((kc8 ^ (row & 7)) << 4)) = d;
                }
            }
        }
        __syncthreads();

        // ---- 3 passes of mma: (hi,hi), (hi,lo), (lo,hi) ----
        float acc[16];
        #pragma unroll
        for (int s = 0; s < 16; ++s) acc[s] = 0.0f;

        #pragma unroll
        for (int pass = 0; pass < 3; ++pass) {
            const uint32_t a_tile = (pass == 2) ? (uint32_t)TILE_B : 0u;       // A_lo : A_hi
            const uint32_t b_tile = (pass == 1) ? (uint32_t)TILE_B : 0u;       // B_lo : B_hi
            #pragma unroll
            for (int ks = 0; ks < KSTEPS; ++ks) {
                const int kb = ks >> 2;
                const int kc_base = (ks & 3) * 2;  // 16B-chunk index of this k16
                uint32_t a[4], b0[4], b1[4];
                {
                    const int kc8 = kc_base + a_kh;
                    ldmatrix_x4(a, a_rb + a_tile + kb * 8192 + ((kc8 ^ a_r7) << 4));
                }
                {
                    const int kc8 = kc_base + b_kh;
                    ldmatrix_x4(b0, b_rb0 + b_tile + kb * 8192 + ((kc8 ^ b_r70) << 4));
                    ldmatrix_x4(b1, b_rb1 + b_tile + kb * 8192 + ((kc8 ^ b_r71) << 4));
                }
                mma_16816(acc + 0,  a, b0 + 0);   // nb0: n 0-7
                mma_16816(acc + 4,  a, b0 + 2);   // nb1: n 8-15
                mma_16816(acc + 8,  a, b1 + 0);   // nb2: n 16-23
                mma_16816(acc + 12, a, b1 + 2);   // nb3: n 24-31
            }
        }

        // ---- stash combo results ----
        #pragma unroll
        for (int s = 0; s < 16; ++s)
            Cs[combo * 4096 + s * 256 + tid] = acc[s];
    }
    __syncthreads();

    // ---- epilogue: batch softmax + |diff|, triangle-weighted ----
    const int g = lid >> 2, t2 = (lid & 3) << 1;
    const bool offdiag = (tj > ti);
    float wsum = 0.0f;
    #pragma unroll
    for (int s = 0; s < 16; ++s) {
        const int nb = s >> 2, q = s & 3;
        const int i = i0 + wrow * 16 + g + ((q & 2) << 2);
        const int j = j0 + wcol * 32 + nb * 8 + t2 + (q & 1);
        const float w = offdiag ? 2.0f : ((j > i) ? 2.0f : ((j == i) ? 1.0f : 0.0f));

        float g1[4], g2[4];
        #pragma unroll
        for (int c = 0; c < 4; ++c) {
            g1[c] = Cs[c * 4096 + s * 256 + tid];
            g2[c] = Cs[(4 + c) * 4096 + s * 256 + tid];
        }
        float m1 = fmaxf(fmaxf(g1[0], g1[1]), fmaxf(g1[2], g1[3]));
        float m2 = fmaxf(fmaxf(g2[0], g2[1]), fmaxf(g2[2], g2[3]));
        float e1[4], e2[4], s1 = 0.0f, s2 = 0.0f;
        #pragma unroll
        for (int c = 0; c < 4; ++c) {
            e1[c] = __expf(g1[c] - m1); s1 += e1[c];
            e2[c] = __expf(g2[c] - m2); s2 += e2[c];
        }
        const float inv1 = __frcp_rn(s1), inv2 = __frcp_rn(s2);
        float d = 0.0f;
        #pragma unroll
        for (int c = 0; c < 4; ++c)
            d += fabsf(e1[c] * inv1 - e2[c] * inv2);
        wsum += w * d;
    }

    // ---- reduce: warp shfl -> smem -> single atomic ----
    #pragma unroll
    for (int s = 16; s; s >>= 1) wsum += __shfl_xor_sync(0xFFFFFFFFu, wsum, s);
    __syncthreads();  // done reading Cs; reuse smem front
    float* wsums = (float*)smem;
    if (lid == 0) wsums[wid] = wsum;
    __syncthreads();
    if (tid == 0) {
        float t = 0.0f;
        #pragma unroll
        for (int wq = 0; wq < 8; ++wq) t += wsums[wq];
        atomicAdd(&g_sum[level], (double)t);
    }
}

__global__ void finalize_kernel(float* out) {
    const double n0 = 4.0 * 4096.0 * 4096.0;
    const double n1 = 4.0 * 1024.0 * 1024.0;
    out[0] = (float)((g_sum[0] / n0 + g_sum[1] / n1) * 0.5);
}

// ============================================================================
// Launch
// ============================================================================
extern "C" void kernel_launch(void* const* d_in, const int* in_sizes, int n_in,
                              void* d_out, int out_size)
{
    const float* fea1_0 = (const float*)d_in[0];  // (4, 64, 64, 64)
    const float* fea1_1 = (const float*)d_in[1];  // (4, 128, 32, 32)
    const float* fea2_0 = (const float*)d_in[2];
    const float* fea2_1 = (const float*)d_in[3];
    float* out = (float*)d_out;

    // smem: 4 tiles + 128KB Cs stash
    const int smem0 = 4 * 8192 + 131072;    // C=64  -> 160 KB
    const int smem1 = 4 * 16384 + 131072;   // C=128 -> 192 KB
    cudaFuncSetAttribute(gram_loss_mma<64>,
                         cudaFuncAttributeMaxDynamicSharedMemorySize, smem0);
    cudaFuncSetAttribute(gram_loss_mma<128>,
                         cudaFuncAttributeMaxDynamicSharedMemorySize, smem1);

    init_sums_kernel<<<1, 1>>>();

    convert_kernel<64><<<dim3(64, 4, 2), 256>>>(fea1_0, fea2_0, 4096, L0_HI, L0_LO);
    convert_kernel<128><<<dim3(16, 4, 2), 256>>>(fea1_1, fea2_1, 1024, L1_HI, L1_LO);

    // level 0: 64x64 tiles of 64
    gram_loss_mma<64><<<dim3(64, 64), 256, smem0>>>(4096, L0_HI, L0_LO, 0);
    // level 1: 16x16 tiles of 64
    gram_loss_mma<128><<<dim3(16, 16), 256, smem1>>>(1024, L1_HI, L1_LO, 1);

    finalize_kernel<<<1, 1>>>(out);
}

// round 4
// speedup vs baseline: 2.0846x; 1.9091x over previous
#include <cuda_runtime.h>
#include <cuda_bf16.h>
#include <cstdint>
#include <math.h>

// ============================================================================
// Globals
// ============================================================================

__device__ double g_sum[2];

// bf16 hi/lo panels, [tb = t*4+b][pos][c] layout (c contiguous):
#define L0_HI 0
#define L0_LO 2097152
#define L1_HI 4194304
#define L1_LO 5242880
__device__ __nv_bfloat16 g_scratch[6291456];

__global__ void init_sums_kernel() { g_sum[0] = 0.0; g_sum[1] = 0.0; }

// ============================================================================
// Pre-convert: fp32 [b][c][pos] -> bf16 hi & lo panels [tb][pos][C]
// ============================================================================
template <int C>
__global__ void __launch_bounds__(256)
convert_kernel(const float* __restrict__ f1, const float* __restrict__ f2,
               int HW, int hi_off, int lo_off)
{
    __shared__ float tile[C * 65];  // [c][pos0..63], padded
    const int t = blockIdx.z, b = blockIdx.y;
    const int pos0 = blockIdx.x * 64;
    const float* src = (t ? f2 : f1) + (size_t)b * C * HW;

    for (int idx = threadIdx.x; idx < C * 64; idx += 256) {
        int c = idx >> 6, p = idx & 63;
        tile[c * 65 + p] = src[(size_t)c * HW + pos0 + p];
    }
    __syncthreads();

    const size_t pb = ((size_t)(t * 4 + b) * HW + pos0) * C;
    __nv_bfloat16* oh = g_scratch + hi_off + pb;
    __nv_bfloat16* ol = g_scratch + lo_off + pb;
    constexpr int CSH = (C == 64) ? 6 : 7;
    for (int idx = threadIdx.x; idx < 64 * C; idx += 256) {
        int p = idx >> CSH, c = idx & (C - 1);
        float v = tile[c * 65 + p];
        __nv_bfloat16 hi = __float2bfloat16(v);
        oh[(size_t)p * C + c] = hi;
        ol[(size_t)p * C + c] = __float2bfloat16(v - __bfloat162float(hi));
    }
}

// ============================================================================
// PTX helpers (sm_80+ vocabulary only -> safe for plain sm_100 ptxas target)
// ============================================================================

__device__ __forceinline__ uint32_t smem_to_u32(const void* p) {
    uint32_t a;
    asm("{ .reg .u64 t; cvta.to.shared.u64 t, %1; cvt.u32.u64 %0, t; }"
        : "=r"(a) : "l"(p));
    return a;
}

__device__ __forceinline__ void ldmatrix_x4(uint32_t* r, uint32_t addr) {
    asm volatile(
        "ldmatrix.sync.aligned.m8n8.x4.shared.b16 {%0,%1,%2,%3}, [%4];"
        : "=r"(r[0]), "=r"(r[1]), "=r"(r[2]), "=r"(r[3]) : "r"(addr));
}

__device__ __forceinline__ void mma_16816(float* d, const uint32_t* a,
                                          const uint32_t* b) {
    asm volatile(
        "mma.sync.aligned.m16n8k16.row.col.f32.bf16.bf16.f32 "
        "{%0,%1,%2,%3}, {%4,%5,%6,%7}, {%8,%9}, {%0,%1,%2,%3};"
        : "+f"(d[0]), "+f"(d[1]), "+f"(d[2]), "+f"(d[3])
        : "r"(a[0]), "r"(a[1]), "r"(a[2]), "r"(a[3]), "r"(b[0]), "r"(b[1]));
}

__device__ __forceinline__ void cp_async16(uint32_t saddr, const void* gaddr) {
    asm volatile("cp.async.cg.shared.global [%0], [%1], 16;"
                 :: "r"(saddr), "l"(gaddr));
}
#define CP_COMMIT() asm volatile("cp.async.commit_group;" ::: "memory")
#define CP_WAIT(n)  asm volatile("cp.async.wait_group %0;" :: "n"(n) : "memory")

// ============================================================================
// Fused Gram (mma.sync, 3-pass hi/lo) + batch-softmax + |diff| partial sum
// Block: 64x64 tile, 8 warps (4 row x 2 col), warp = 16m x 32n.
// Multi-stage cp.async pipeline over the 8 (tensor,batch) combos.
// ============================================================================
template <int C, int NSTAGES>
__global__ void __launch_bounds__(256, 1)
gram_loss_mma(int HW, int hi_off, int lo_off, int level)
{
    const int ti = blockIdx.y, tj = blockIdx.x;
    if (tj < ti) return;  // upper triangle only

    constexpr int TILE_B = (C / 64) * 8192;  // one 64-row tile, bytes
    constexpr int STAGE_B = 4 * TILE_B;      // A_hi|A_lo|B_hi|B_lo
    constexpr int NCH = C / 8;               // 16B chunks per row
    constexpr int KSTEPS = C / 16;

    extern __shared__ char smem[];
    const uint32_t sb = smem_to_u32(smem);
    float* Cs = (float*)(smem + NSTAGES * STAGE_B);  // [combo][slot][tid]

    const int tid = threadIdx.x;
    const int wid = tid >> 5, lid = tid & 31;
    const int wrow = wid & 3, wcol = wid >> 2;
    const int i0 = ti * 64, j0 = tj * 64;

    // ---- stage loader: cp.async all 4 tiles of one combo into a stage ----
    const size_t HWC = (size_t)HW * C;
    auto load_stage = [&](int combo, int stage) {
        const size_t pbase = (size_t)combo * HWC;
        const __nv_bfloat16* srcs[4] = {
            g_scratch + hi_off + pbase + (size_t)i0 * C,
            g_scratch + lo_off + pbase + (size_t)i0 * C,
            g_scratch + hi_off + pbase + (size_t)j0 * C,
            g_scratch + lo_off + pbase + (size_t)j0 * C };
        const uint32_t stb = sb + stage * STAGE_B;
        #pragma unroll
        for (int tile = 0; tile < 4; ++tile) {
            const __nv_bfloat16* s = srcs[tile];
            const uint32_t dst = stb + tile * TILE_B;
            #pragma unroll
            for (int p = 0; p < (64 * NCH) / 256; ++p) {
                const int v = p * 256 + tid;
                const int row = v / NCH, kcq = v % NCH;
                const int kb = kcq >> 3, kc8 = kcq & 7;
                cp_async16(dst + kb * 8192 + row * 128 + ((kc8 ^ (row & 7)) << 4),
                           s + (size_t)row * C + kcq * 8);
            }
        }
    };

    // ---- per-lane ldmatrix addressing (stage-invariant parts) ----
    const int mat = lid >> 3, lrow = lid & 7;
    const int a_row = wrow * 16 + ((mat & 1) << 3) + lrow;
    const int a_kh = mat >> 1;
    const int b_kh = mat & 1;
    const int b_row0 = wcol * 32 + ((mat >> 1) << 3) + lrow;
    const int b_row1 = b_row0 + 16;
    const uint32_t a_ro = a_row * 128;                    // within A tile
    const uint32_t b_ro0 = 2 * TILE_B + b_row0 * 128;     // within stage
    const uint32_t b_ro1 = 2 * TILE_B + b_row1 * 128;
    const int a_r7 = a_row & 7, b_r70 = b_row0 & 7, b_r71 = b_row1 & 7;

    if (NSTAGES > 1) {
        load_stage(0, 0); CP_COMMIT();
        load_stage(1, 1); CP_COMMIT();
    }

    #pragma unroll 1
    for (int combo = 0; combo < 8; ++combo) {
        const int stage = (NSTAGES > 1) ? (combo % NSTAGES) : 0;
        if (NSTAGES > 1) {
            if (combo < 7) { CP_WAIT(1); } else { CP_WAIT(0); }
            __syncthreads();            // combo's data visible; prev readers done
            if (combo + 2 < 8) {
                load_stage(combo + 2, (combo + 2) % NSTAGES);
                CP_COMMIT();
            }
        } else {
            __syncthreads();            // prior combo's readers done
            load_stage(combo, 0); CP_COMMIT();
            CP_WAIT(0);
            __syncthreads();
        }

        const uint32_t stb = sb + stage * STAGE_B;
        const uint32_t a_rb = stb + a_ro;
        const uint32_t b_rb0 = stb + b_ro0;
        const uint32_t b_rb1 = stb + b_ro1;

        // ---- 3 passes of mma: (hi,hi), (hi,lo), (lo,hi) ----
        float acc[16];
        #pragma unroll
        for (int s = 0; s < 16; ++s) acc[s] = 0.0f;

        #pragma unroll
        for (int pass = 0; pass < 3; ++pass) {
            const uint32_t a_tile = (pass == 2) ? (uint32_t)TILE_B : 0u;  // A_lo : A_hi
            const uint32_t b_tile = (pass == 1) ? (uint32_t)TILE_B : 0u;  // B_lo : B_hi
            #pragma unroll
            for (int ks = 0; ks < KSTEPS; ++ks) {
                const int kb = ks >> 2;
                const int kc_base = (ks & 3) * 2;
                uint32_t a[4], b0[4], b1[4];
                {
                    const int kc8 = kc_base + a_kh;
                    ldmatrix_x4(a, a_rb + a_tile + kb * 8192 + ((kc8 ^ a_r7) << 4));
                }
                {
                    const int kc8 = kc_base + b_kh;
                    ldmatrix_x4(b0, b_rb0 + b_tile + kb * 8192 + ((kc8 ^ b_r70) << 4));
                    ldmatrix_x4(b1, b_rb1 + b_tile + kb * 8192 + ((kc8 ^ b_r71) << 4));
                }
                mma_16816(acc + 0,  a, b0 + 0);
                mma_16816(acc + 4,  a, b0 + 2);
                mma_16816(acc + 8,  a, b1 + 0);
                mma_16816(acc + 12, a, b1 + 2);
            }
        }

        // ---- stash combo results ----
        #pragma unroll
        for (int s = 0; s < 16; ++s)
            Cs[combo * 4096 + s * 256 + tid] = acc[s];
    }
    __syncthreads();

    // ---- epilogue: batch softmax + |diff|, triangle-weighted ----
    const int g = lid >> 2, t2 = (lid & 3) << 1;
    const bool offdiag = (tj > ti);
    float wsum = 0.0f;
    #pragma unroll
    for (int s = 0; s < 16; ++s) {
        const int nb = s >> 2, q = s & 3;
        const int i = i0 + wrow * 16 + g + ((q & 2) << 2);
        const int j = j0 + wcol * 32 + nb * 8 + t2 + (q & 1);
        const float w = offdiag ? 2.0f : ((j > i) ? 2.0f : ((j == i) ? 1.0f : 0.0f));

        float g1[4], g2[4];
        #pragma unroll
        for (int c = 0; c < 4; ++c) {
            g1[c] = Cs[c * 4096 + s * 256 + tid];
            g2[c] = Cs[(4 + c) * 4096 + s * 256 + tid];
        }
        float m1 = fmaxf(fmaxf(g1[0], g1[1]), fmaxf(g1[2], g1[3]));
        float m2 = fmaxf(fmaxf(g2[0], g2[1]), fmaxf(g2[2], g2[3]));
        float e1[4], e2[4], s1 = 0.0f, s2 = 0.0f;
        #pragma unroll
        for (int c = 0; c < 4; ++c) {
            e1[c] = __expf(g1[c] - m1); s1 += e1[c];
            e2[c] = __expf(g2[c] - m2); s2 += e2[c];
        }
        const float inv1 = __frcp_rn(s1), inv2 = __frcp_rn(s2);
        float d = 0.0f;
        #pragma unroll
        for (int c = 0; c < 4; ++c)
            d += fabsf(e1[c] * inv1 - e2[c] * inv2);
        wsum += w * d;
    }

    // ---- reduce: warp shfl -> smem -> single atomic ----
    #pragma unroll
    for (int s = 16; s; s >>= 1) wsum += __shfl_xor_sync(0xFFFFFFFFu, wsum, s);
    __syncthreads();
    float* wsums = (float*)smem;
    if (lid == 0) wsums[wid] = wsum;
    __syncthreads();
    if (tid == 0) {
        float t = 0.0f;
        #pragma unroll
        for (int wq = 0; wq < 8; ++wq) t += wsums[wq];
        atomicAdd(&g_sum[level], (double)t);
    }
}

__global__ void finalize_kernel(float* out) {
    const double n0 = 4.0 * 4096.0 * 4096.0;
    const double n1 = 4.0 * 1024.0 * 1024.0;
    out[0] = (float)((g_sum[0] / n0 + g_sum[1] / n1) * 0.5);
}

// ============================================================================
// Launch
// ============================================================================
extern "C" void kernel_launch(void* const* d_in, const int* in_sizes, int n_in,
                              void* d_out, int out_size)
{
    const float* fea1_0 = (const float*)d_in[0];  // (4, 64, 64, 64)
    const float* fea1_1 = (const float*)d_in[1];  // (4, 128, 32, 32)
    const float* fea2_0 = (const float*)d_in[2];
    const float* fea2_1 = (const float*)d_in[3];
    float* out = (float*)d_out;

    // smem: stages + 128KB Cs stash
    const int smem0 = 3 * 32768 + 131072;   // C=64,  3 stages -> 224 KB
    const int smem1 = 1 * 65536 + 131072;   // C=128, 1 stage  -> 192 KB
    cudaFuncSetAttribute(gram_loss_mma<64, 3>,
                         cudaFuncAttributeMaxDynamicSharedMemorySize, smem0);
    cudaFuncSetAttribute(gram_loss_mma<128, 1>,
                         cudaFuncAttributeMaxDynamicSharedMemorySize, smem1);

    init_sums_kernel<<<1, 1>>>();

    convert_kernel<64><<<dim3(64, 4, 2), 256>>>(fea1_0, fea2_0, 4096, L0_HI, L0_LO);
    convert_kernel<128><<<dim3(16, 4, 2), 256>>>(fea1_1, fea2_1, 1024, L1_HI, L1_LO);

    gram_loss_mma<64, 3><<<dim3(64, 64), 256, smem0>>>(4096, L0_HI, L0_LO, 0);
    gram_loss_mma<128, 1><<<dim3(16, 16), 256, smem1>>>(1024, L1_HI, L1_LO, 1);

    finalize_kernel<<<1, 1>>>(out);
}

// round 5
// speedup vs baseline: 2.5041x; 1.2012x over previous
#include <cuda_runtime.h>
#include <cuda_bf16.h>
#include <cstdint>
#include <math.h>

// ============================================================================
// Globals
// ============================================================================

__device__ double g_sum[2];

// bf16 hi/lo panels, [tb = t*4+b][pos][c] layout (c contiguous):
#define L0_HI 0
#define L0_LO 2097152
#define L1_HI 4194304
#define L1_LO 5242880
__device__ __nv_bfloat16 g_scratch[6291456];

__global__ void init_sums_kernel() { g_sum[0] = 0.0; g_sum[1] = 0.0; }

// ============================================================================
// Pre-convert: fp32 [b][c][pos] -> bf16 hi & lo panels [tb][pos][C]
// ============================================================================
template <int C>
__global__ void __launch_bounds__(256)
convert_kernel(const float* __restrict__ f1, const float* __restrict__ f2,
               int HW, int hi_off, int lo_off)
{
    __shared__ float tile[C * 65];  // [c][pos0..63], padded
    const int t = blockIdx.z, b = blockIdx.y;
    const int pos0 = blockIdx.x * 64;
    const float* src = (t ? f2 : f1) + (size_t)b * C * HW;

    for (int idx = threadIdx.x; idx < C * 64; idx += 256) {
        int c = idx >> 6, p = idx & 63;
        tile[c * 65 + p] = src[(size_t)c * HW + pos0 + p];
    }
    __syncthreads();

    const size_t pb = ((size_t)(t * 4 + b) * HW + pos0) * C;
    __nv_bfloat16* oh = g_scratch + hi_off + pb;
    __nv_bfloat16* ol = g_scratch + lo_off + pb;
    constexpr int CSH = (C == 64) ? 6 : 7;
    for (int idx = threadIdx.x; idx < 64 * C; idx += 256) {
        int p = idx >> CSH, c = idx & (C - 1);
        float v = tile[c * 65 + p];
        __nv_bfloat16 hi = __float2bfloat16(v);
        oh[(size_t)p * C + c] = hi;
        ol[(size_t)p * C + c] = __float2bfloat16(v - __bfloat162float(hi));
    }
}

// ============================================================================
// PTX helpers (sm_80+ vocabulary only -> safe for plain sm_100 ptxas target)
// ============================================================================

__device__ __forceinline__ uint32_t smem_to_u32(const void* p) {
    uint32_t a;
    asm("{ .reg .u64 t; cvta.to.shared.u64 t, %1; cvt.u32.u64 %0, t; }"
        : "=r"(a) : "l"(p));
    return a;
}

__device__ __forceinline__ void ldmatrix_x4(uint32_t* r, uint32_t addr) {
    asm volatile(
        "ldmatrix.sync.aligned.m8n8.x4.shared.b16 {%0,%1,%2,%3}, [%4];"
        : "=r"(r[0]), "=r"(r[1]), "=r"(r[2]), "=r"(r[3]) : "r"(addr));
}

__device__ __forceinline__ void mma_16816(float* d, const uint32_t* a,
                                          const uint32_t* b) {
    asm volatile(
        "mma.sync.aligned.m16n8k16.row.col.f32.bf16.bf16.f32 "
        "{%0,%1,%2,%3}, {%4,%5,%6,%7}, {%8,%9}, {%0,%1,%2,%3};"
        : "+f"(d[0]), "+f"(d[1]), "+f"(d[2]), "+f"(d[3])
        : "r"(a[0]), "r"(a[1]), "r"(a[2]), "r"(a[3]), "r"(b[0]), "r"(b[1]));
}

__device__ __forceinline__ void cp_async16(uint32_t saddr, const void* gaddr) {
    asm volatile("cp.async.cg.shared.global [%0], [%1], 16;"
                 :: "r"(saddr), "l"(gaddr));
}
#define CP_COMMIT() asm volatile("cp.async.commit_group;" ::: "memory")
#define CP_WAIT(n)  asm volatile("cp.async.wait_group %0;" :: "n"(n) : "memory")

// ============================================================================
// Fused Gram (mma.sync, 3-pass hi/lo) + two-phase batch-softmax + |diff|.
// Block: 64(i) x 32(j) tile, 8 warps (4 row x 2 col), warp = 16m x 16n.
// Registers hold the 4 per-tensor batch accumulators; phase 1 stores softmaxed
// aff1 to smem (32 KB), phase 2 diffs. 2 CTAs/SM for level 0.
// ============================================================================
template <int C, int NSTAGES, int MINB>
__global__ void __launch_bounds__(256, MINB)
gram_loss_mma(int HW, int hi_off, int lo_off, int level)
{
    const int ti = blockIdx.y, tj = blockIdx.x;
    if (tj < 2 * ti) return;  // tile entirely below diagonal

    constexpr int NCH = C / 8;                 // 16B chunks per row
    constexpr int A_TILE = C * 128;            // 64 rows
    constexpr int B_TILE = C * 64;             // 32 rows
    constexpr int STAGE_B = 2 * A_TILE + 2 * B_TILE;
    constexpr int KSTEPS = C / 16;

    extern __shared__ char smem[];
    const uint32_t sb = smem_to_u32(smem);
    float* aff = (float*)(smem + NSTAGES * STAGE_B);  // [b*8+s][tid] = 32 KB

    const int tid = threadIdx.x, wid = tid >> 5, lid = tid & 31;
    const int wrow = wid & 3, wcol = wid >> 2;
    const int i0 = ti * 64, j0 = tj * 32;

    const size_t HWC = (size_t)HW * C;
    auto load_stage = [&](int combo, int stage) {
        const size_t pbase = (size_t)combo * HWC;
        const uint32_t stb = sb + stage * STAGE_B;
        #pragma unroll
        for (int hl = 0; hl < 2; ++hl) {       // A tiles: 64 rows at i0
            const __nv_bfloat16* s = g_scratch + (hl ? lo_off : hi_off)
                                     + pbase + (size_t)i0 * C;
            const uint32_t dst = stb + hl * A_TILE;
            #pragma unroll
            for (int p = 0; p < (64 * NCH) / 256; ++p) {
                int v = p * 256 + tid;
                int row = v / NCH, kcq = v % NCH;
                cp_async16(dst + (kcq >> 3) * 8192 + row * 128 +
                               (((kcq & 7) ^ (row & 7)) << 4),
                           s + (size_t)row * C + kcq * 8);
            }
        }
        #pragma unroll
        for (int hl = 0; hl < 2; ++hl) {       // B tiles: 32 rows at j0
            const __nv_bfloat16* s = g_scratch + (hl ? lo_off : hi_off)
                                     + pbase + (size_t)j0 * C;
            const uint32_t dst = stb + 2 * A_TILE + hl * B_TILE;
            #pragma unroll
            for (int p = 0; p < (32 * NCH) / 256; ++p) {
                int v = p * 256 + tid;
                int row = v / NCH, kcq = v % NCH;
                cp_async16(dst + (kcq >> 3) * 4096 + row * 128 +
                               (((kcq & 7) ^ (row & 7)) << 4),
                           s + (size_t)row * C + kcq * 8);
            }
        }
    };

    // ---- per-lane ldmatrix addressing (stage-invariant) ----
    const int mat = lid >> 3, lrow = lid & 7;
    const int a_row = wrow * 16 + ((mat & 1) << 3) + lrow;
    const int a_kh = mat >> 1;
    const int b_row = wcol * 16 + ((mat >> 1) << 3) + lrow;
    const int b_kh = mat & 1;
    const uint32_t a_off = a_row * 128;
    const uint32_t b_off = 2 * A_TILE + b_row * 128;
    const int a_r7 = a_row & 7, b_r7 = b_row & 7;

    load_stage(0, 0); CP_COMMIT();
    load_stage(1, 1); CP_COMMIT();

    float acc[4][8];
    float wsum = 0.0f;
    const bool fullabove = (tj >= 2 * ti + 2);
    const int gi = lid >> 2, gj = (lid & 3) << 1;

    #pragma unroll 1
    for (int t = 0; t < 2; ++t) {
        #pragma unroll
        for (int b = 0; b < 4; ++b) {
            const int combo = t * 4 + b;
            if (b == 3) { if (t == 1) { CP_WAIT(0); } else { CP_WAIT(1); } }
            else        { CP_WAIT(1); }
            __syncthreads();  // combo's stage ready; prior readers done
            if (combo + 2 < 8) {
                load_stage(combo + 2, (combo + 2) % NSTAGES);
                CP_COMMIT();
            }

            const uint32_t stb = sb + (combo % NSTAGES) * STAGE_B;
            #pragma unroll
            for (int s = 0; s < 8; ++s) acc[b][s] = 0.0f;

            #pragma unroll
            for (int pass = 0; pass < 3; ++pass) {
                const uint32_t a_t = stb + ((pass == 2) ? A_TILE : 0) + a_off;
                const uint32_t b_t = stb + ((pass == 1) ? B_TILE : 0) + b_off;
                #pragma unroll
                for (int ks = 0; ks < KSTEPS; ++ks) {
                    const int kb = ks >> 2, kc = (ks & 3) * 2;
                    uint32_t a[4], bb[4];
                    ldmatrix_x4(a,  a_t + kb * 8192 + (((kc + a_kh) ^ a_r7) << 4));
                    ldmatrix_x4(bb, b_t + kb * 4096 + (((kc + b_kh) ^ b_r7) << 4));
                    mma_16816(acc[b] + 0, a, bb + 0);   // n 0-7
                    mma_16816(acc[b] + 4, a, bb + 2);   // n 8-15
                }
            }
        }

        // ---- per-phase epilogue ----
        if (t == 0) {
            // softmax over batch of tensor 1 -> aff smem buffer (thread-private slots)
            #pragma unroll
            for (int s = 0; s < 8; ++s) {
                float m1 = fmaxf(fmaxf(acc[0][s], acc[1][s]),
                                 fmaxf(acc[2][s], acc[3][s]));
                float e[4], sum = 0.0f;
                #pragma unroll
                for (int b2 = 0; b2 < 4; ++b2) {
                    e[b2] = __expf(acc[b2][s] - m1); sum += e[b2];
                }
                const float inv = __frcp_rn(sum);
                #pragma unroll
                for (int b2 = 0; b2 < 4; ++b2)
                    aff[(b2 * 8 + s) * 256 + tid] = e[b2] * inv;
            }
        } else {
            #pragma unroll
            for (int s = 0; s < 8; ++s) {
                const int nb = s >> 2, q = s & 3;
                const int i = i0 + wrow * 16 + gi + ((q & 2) << 2);
                const int j = j0 + wcol * 16 + nb * 8 + gj + (q & 1);
                const float w = fullabove ? 2.0f
                              : ((j > i) ? 2.0f : ((j == i) ? 1.0f : 0.0f));
                float m2 = fmaxf(fmaxf(acc[0][s], acc[1][s]),
                                 fmaxf(acc[2][s], acc[3][s]));
                float e[4], sum = 0.0f;
                #pragma unroll
                for (int b2 = 0; b2 < 4; ++b2) {
                    e[b2] = __expf(acc[b2][s] - m2); sum += e[b2];
                }
                const float inv = __frcp_rn(sum);
                float d = 0.0f;
                #pragma unroll
                for (int b2 = 0; b2 < 4; ++b2)
                    d += fabsf(aff[(b2 * 8 + s) * 256 + tid] - e[b2] * inv);
                wsum += w * d;
            }
        }
    }

    // ---- reduce: warp shfl -> smem -> single atomic ----
    #pragma unroll
    for (int s2 = 16; s2; s2 >>= 1) wsum += __shfl_xor_sync(0xFFFFFFFFu, wsum, s2);
    __syncthreads();             // all stage/aff reads done; reuse smem front
    float* wsums = (float*)smem;
    if (lid == 0) wsums[wid] = wsum;
    __syncthreads();
    if (tid == 0) {
        float tt = 0.0f;
        #pragma unroll
        for (int wq = 0; wq < 8; ++wq) tt += wsums[wq];
        atomicAdd(&g_sum[level], (double)tt);
    }
}

__global__ void finalize_kernel(float* out) {
    const double n0 = 4.0 * 4096.0 * 4096.0;
    const double n1 = 4.0 * 1024.0 * 1024.0;
    out[0] = (float)((g_sum[0] / n0 + g_sum[1] / n1) * 0.5);
}

// ============================================================================
// Launch
// ============================================================================
extern "C" void kernel_launch(void* const* d_in, const int* in_sizes, int n_in,
                              void* d_out, int out_size)
{
    const float* fea1_0 = (const float*)d_in[0];  // (4, 64, 64, 64)
    const float* fea1_1 = (const float*)d_in[1];  // (4, 128, 32, 32)
    const float* fea2_0 = (const float*)d_in[2];
    const float* fea2_1 = (const float*)d_in[3];
    float* out = (float*)d_out;

    // smem: NSTAGES * stage + 32KB aff buffer
    const int smem0 = 3 * 24576 + 32768;    // C=64  -> 104 KB, 2 CTAs/SM
    const int smem1 = 3 * 49152 + 32768;    // C=128 -> 176 KB, 1 CTA/SM
    cudaFuncSetAttribute(gram_loss_mma<64, 3, 2>,
                         cudaFuncAttributeMaxDynamicSharedMemorySize, smem0);
    cudaFuncSetAttribute(gram_loss_mma<128, 3, 1>,
                         cudaFuncAttributeMaxDynamicSharedMemorySize, smem1);

    init_sums_kernel<<<1, 1>>>();

    convert_kernel<64><<<dim3(64, 4, 2), 256>>>(fea1_0, fea2_0, 4096, L0_HI, L0_LO);
    convert_kernel<128><<<dim3(16, 4, 2), 256>>>(fea1_1, fea2_1, 1024, L1_HI, L1_LO);

    // level 0: 64 i-tiles (64 rows) x 128 j-tiles (32 cols)
    gram_loss_mma<64, 3, 2><<<dim3(128, 64), 256, smem0>>>(4096, L0_HI, L0_LO, 0);
    // level 1: 16 i-tiles x 32 j-tiles
    gram_loss_mma<128, 3, 1><<<dim3(32, 16), 256, smem1>>>(1024, L1_HI, L1_LO, 1);

    finalize_kernel<<<1, 1>>>(out);
}

// round 7
// speedup vs baseline: 3.1479x; 1.2571x over previous
#include <cuda_runtime.h>
#include <cuda_bf16.h>
#include <cstdint>
#include <math.h>

// ============================================================================
// Globals
// ============================================================================

__device__ double g_sum[2];

// bf16 hi/lo panels, [tb = t*4+b][pos][c] layout (c contiguous):
#define L0_HI 0
#define L0_LO 2097152
#define L1_HI 4194304
#define L1_LO 5242880
__device__ __nv_bfloat16 g_scratch[6291456];

__global__ void init_sums_kernel() { g_sum[0] = 0.0; g_sum[1] = 0.0; }

// ============================================================================
// Pre-convert: fp32 [b][c][pos] -> bf16 hi & lo panels [tb][pos][C]
// ============================================================================
template <int C>
__global__ void __launch_bounds__(256)
convert_kernel(const float* __restrict__ f1, const float* __restrict__ f2,
               int HW, int hi_off, int lo_off)
{
    __shared__ float tile[C * 65];  // [c][pos0..63], padded
    const int t = blockIdx.z, b = blockIdx.y;
    const int pos0 = blockIdx.x * 64;
    const float* src = (t ? f2 : f1) + (size_t)b * C * HW;

    for (int idx = threadIdx.x; idx < C * 64; idx += 256) {
        int c = idx >> 6, p = idx & 63;
        tile[c * 65 + p] = src[(size_t)c * HW + pos0 + p];
    }
    __syncthreads();

    const size_t pb = ((size_t)(t * 4 + b) * HW + pos0) * C;
    __nv_bfloat16* oh = g_scratch + hi_off + pb;
    __nv_bfloat16* ol = g_scratch + lo_off + pb;
    constexpr int CSH = (C == 64) ? 6 : 7;
    for (int idx = threadIdx.x; idx < 64 * C; idx += 256) {
        int p = idx >> CSH, c = idx & (C - 1);
        float v = tile[c * 65 + p];
        __nv_bfloat16 hi = __float2bfloat16(v);
        oh[(size_t)p * C + c] = hi;
        ol[(size_t)p * C + c] = __float2bfloat16(v - __bfloat162float(hi));
    }
}

// ============================================================================
// PTX helpers (sm_80+ vocabulary only -> safe for plain sm_100 ptxas target)
// ============================================================================

__device__ __forceinline__ uint32_t smem_to_u32(const void* p) {
    uint32_t a;
    asm("{ .reg .u64 t; cvta.to.shared.u64 t, %1; cvt.u32.u64 %0, t; }"
        : "=r"(a) : "l"(p));
    return a;
}

__device__ __forceinline__ void ldmatrix_x4(uint32_t* r, uint32_t addr) {
    asm volatile(
        "ldmatrix.sync.aligned.m8n8.x4.shared.b16 {%0,%1,%2,%3}, [%4];"
        : "=r"(r[0]), "=r"(r[1]), "=r"(r[2]), "=r"(r[3]) : "r"(addr));
}

__device__ __forceinline__ void mma_16816(float* d, const uint32_t* a,
                                          const uint32_t* b) {
    asm volatile(
        "mma.sync.aligned.m16n8k16.row.col.f32.bf16.bf16.f32 "
        "{%0,%1,%2,%3}, {%4,%5,%6,%7}, {%8,%9}, {%0,%1,%2,%3};"
        : "+f"(d[0]), "+f"(d[1]), "+f"(d[2]), "+f"(d[3])
        : "r"(a[0]), "r"(a[1]), "r"(a[2]), "r"(a[3]), "r"(b[0]), "r"(b[1]));
}

__device__ __forceinline__ void cp_async16(uint32_t saddr, const void* gaddr) {
    asm volatile("cp.async.cg.shared.global [%0], [%1], 16;"
                 :: "r"(saddr), "l"(gaddr));
}
#define CP_COMMIT() asm volatile("cp.async.commit_group;" ::: "memory")
#define CP_WAIT(n)  asm volatile("cp.async.wait_group %0;" :: "n"(n) : "memory")

// ============================================================================
// Fused Gram (mma.sync, 2-panel: A_hi x (B_hi + B_lo)) + two-phase
// batch-softmax + |diff|.  Block: 64(i) x 32(j), 8 warps (4x2), warp 16x16.
// Stage = A_hi | B_hi | B_lo.  aff1 stored as packed bf16x2.
// ============================================================================
template <int C, int NSTAGES>
__global__ void __launch_bounds__(256, 2)
gram_loss_mma(int HW, int hi_off, int lo_off, int level)
{
    const int ti = blockIdx.y, tj = blockIdx.x;
    if (tj < 2 * ti) return;  // tile entirely below diagonal

    constexpr int NCH = C / 8;                 // 16B chunks per row
    constexpr int A_TILE = C * 128;            // 64 rows (hi only)
    constexpr int B_TILE = C * 64;             // 32 rows
    constexpr int STAGE_B = A_TILE + 2 * B_TILE;
    constexpr int KSTEPS = C / 16;

    extern __shared__ char smem[];
    const uint32_t sb = smem_to_u32(smem);
    __nv_bfloat162* aff = (__nv_bfloat162*)(smem + NSTAGES * STAGE_B);  // [s*2+p][tid]

    const int tid = threadIdx.x, wid = tid >> 5, lid = tid & 31;
    const int wrow = wid & 3, wcol = wid >> 2;
    const int i0 = ti * 64, j0 = tj * 32;

    const size_t HWC = (size_t)HW * C;
    auto load_stage = [&](int combo, int stage) {
        const size_t pbase = (size_t)combo * HWC;
        const uint32_t stb = sb + stage * STAGE_B;
        {   // A_hi: 64 rows at i0
            const __nv_bfloat16* s = g_scratch + hi_off + pbase + (size_t)i0 * C;
            #pragma unroll
            for (int p = 0; p < (64 * NCH) / 256; ++p) {
                int v = p * 256 + tid;
                int row = v / NCH, kcq = v % NCH;
                cp_async16(stb + (kcq >> 3) * 8192 + row * 128 +
                               (((kcq & 7) ^ (row & 7)) << 4),
                           s + (size_t)row * C + kcq * 8);
            }
        }
        #pragma unroll
        for (int hl = 0; hl < 2; ++hl) {       // B_hi, B_lo: 32 rows at j0
            const __nv_bfloat16* s = g_scratch + (hl ? lo_off : hi_off)
                                     + pbase + (size_t)j0 * C;
            const uint32_t dst = stb + A_TILE + hl * B_TILE;
            #pragma unroll
            for (int p = 0; p < (32 * NCH) / 256; ++p) {
                int v = p * 256 + tid;
                int row = v / NCH, kcq = v % NCH;
                cp_async16(dst + (kcq >> 3) * 4096 + row * 128 +
                               (((kcq & 7) ^ (row & 7)) << 4),
                           s + (size_t)row * C + kcq * 8);
            }
        }
    };

    // ---- per-lane ldmatrix addressing (stage-invariant) ----
    const int mat = lid >> 3, lrow = lid & 7;
    const int a_row = wrow * 16 + ((mat & 1) << 3) + lrow;
    const int a_kh = mat >> 1;
    const int b_row = wcol * 16 + ((mat >> 1) << 3) + lrow;
    const int b_kh = mat & 1;
    const uint32_t a_off = a_row * 128;
    const uint32_t b_off = A_TILE + b_row * 128;
    const int a_r7 = a_row & 7, b_r7 = b_row & 7;

    load_stage(0, 0); CP_COMMIT();
    load_stage(1, 1); CP_COMMIT();

    float acc[4][8];
    float wsum = 0.0f;
    const bool fullabove = (tj >= 2 * ti + 2);
    const int gi = lid >> 2, gj = (lid & 3) << 1;

    #pragma unroll 1
    for (int t = 0; t < 2; ++t) {
        #pragma unroll
        for (int b = 0; b < 4; ++b) {
            const int combo = t * 4 + b;
            if (combo == 7) { CP_WAIT(0); } else { CP_WAIT(1); }
            __syncthreads();  // combo's stage ready; prior readers done
            if (combo + 2 < 8) {
                load_stage(combo + 2, (combo + 2) % NSTAGES);
                CP_COMMIT();
            }

            const uint32_t stb = sb + (combo % NSTAGES) * STAGE_B;
            const uint32_t a_t = stb + a_off;
            const uint32_t b_t = stb + b_off;
            #pragma unroll
            for (int s = 0; s < 8; ++s) acc[b][s] = 0.0f;

            #pragma unroll
            for (int ks = 0; ks < KSTEPS; ++ks) {
                const int kb = ks >> 2, kc = (ks & 3) * 2;
                uint32_t a[4], bh[4], bl[4];
                ldmatrix_x4(a,  a_t + kb * 8192 + (((kc + a_kh) ^ a_r7) << 4));
                ldmatrix_x4(bh, b_t + kb * 4096 + (((kc + b_kh) ^ b_r7) << 4));
                ldmatrix_x4(bl, b_t + B_TILE + kb * 4096 +
                                 (((kc + b_kh) ^ b_r7) << 4));
                mma_16816(acc[b] + 0, a, bh + 0);   // n 0-7   (hi)
                mma_16816(acc[b] + 4, a, bh + 2);   // n 8-15  (hi)
                mma_16816(acc[b] + 0, a, bl + 0);   // n 0-7   (lo)
                mma_16816(acc[b] + 4, a, bl + 2);   // n 8-15  (lo)
            }
        }

        // ---- per-phase epilogue ----
        if (t == 0) {
            // softmax over batch of tensor 1 -> aff smem (packed bf16x2)
            #pragma unroll
            for (int s = 0; s < 8; ++s) {
                float m1 = fmaxf(fmaxf(acc[0][s], acc[1][s]),
                                 fmaxf(acc[2][s], acc[3][s]));
                float e[4], sum = 0.0f;
                #pragma unroll
                for (int b2 = 0; b2 < 4; ++b2) {
                    e[b2] = __expf(acc[b2][s] - m1); sum += e[b2];
                }
                const float inv = __frcp_rn(sum);
                aff[(s * 2 + 0) * 256 + tid] =
                    __floats2bfloat162_rn(e[0] * inv, e[1] * inv);
                aff[(s * 2 + 1) * 256 + tid] =
                    __floats2bfloat162_rn(e[2] * inv, e[3] * inv);
            }
        } else {
            #pragma unroll
            for (int s = 0; s < 8; ++s) {
                const int nb = s >> 2, q = s & 3;
                const int i = i0 + wrow * 16 + gi + ((q & 2) << 2);
                const int j = j0 + wcol * 16 + nb * 8 + gj + (q & 1);
                const float w = fullabove ? 2.0f
                              : ((j > i) ? 2.0f : ((j == i) ? 1.0f : 0.0f));
                float m2 = fmaxf(fmaxf(acc[0][s], acc[1][s]),
                                 fmaxf(acc[2][s], acc[3][s]));
                float e[4], sum = 0.0f;
                #pragma unroll
                for (int b2 = 0; b2 < 4; ++b2) {
                    e[b2] = __expf(acc[b2][s] - m2); sum += e[b2];
                }
                const float inv = __frcp_rn(sum);
                const float2 a01 = __bfloat1622float2(aff[(s * 2 + 0) * 256 + tid]);
                const float2 a23 = __bfloat1622float2(aff[(s * 2 + 1) * 256 + tid]);
                float d = fabsf(a01.x - e[0] * inv) + fabsf(a01.y - e[1] * inv)
                        + fabsf(a23.x - e[2] * inv) + fabsf(a23.y - e[3] * inv);
                wsum += w * d;
            }
        }
    }

    // ---- reduce: warp shfl -> smem -> single atomic ----
    #pragma unroll
    for (int s2 = 16; s2; s2 >>= 1) wsum += __shfl_xor_sync(0xFFFFFFFFu, wsum, s2);
    __syncthreads();             // all stage/aff reads done; reuse smem front
    float* wsums = (float*)smem;
    if (lid == 0) wsums[wid] = wsum;
    __syncthreads();
    if (tid == 0) {
        float tt = 0.0f;
        #pragma unroll
        for (int wq = 0; wq < 8; ++wq) tt += wsums[wq];
        atomicAdd(&g_sum[level], (double)tt);
    }
}

__global__ void finalize_kernel(float* out) {
    const double n0 = 4.0 * 4096.0 * 4096.0;
    const double n1 = 4.0 * 1024.0 * 1024.0;
    out[0] = (float)((g_sum[0] / n0 + g_sum[1] / n1) * 0.5);
}

// ============================================================================
// Launch
// ============================================================================
extern "C" void kernel_launch(void* const* d_in, const int* in_sizes, int n_in,
                              void* d_out, int out_size)
{
    const float* fea1_0 = (const float*)d_in[0];  // (4, 64, 64, 64)
    const float* fea1_1 = (const float*)d_in[1];  // (4, 128, 32, 32)
    const float* fea2_0 = (const float*)d_in[2];
    const float* fea2_1 = (const float*)d_in[3];
    float* out = (float*)d_out;

    // smem: NSTAGES * stage + 16KB bf16 aff buffer
    const int smem0 = 3 * 16384 + 16384;    // C=64  -> 64 KB,  2 CTAs/SM
    const int smem1 = 3 * 32768 + 16384;    // C=128 -> 112 KB, 2 CTAs/SM
    cudaFuncSetAttribute(gram_loss_mma<64, 3>,
                         cudaFuncAttributeMaxDynamicSharedMemorySize, smem0);
    cudaFuncSetAttribute(gram_loss_mma<128, 3>,
                         cudaFuncAttributeMaxDynamicSharedMemorySize, smem1);

    init_sums_kernel<<<1, 1>>>();

    convert_kernel<64><<<dim3(64, 4, 2), 256>>>(fea1_0, fea2_0, 4096, L0_HI, L0_LO);
    convert_kernel<128><<<dim3(16, 4, 2), 256>>>(fea1_1, fea2_1, 1024, L1_HI, L1_LO);

    // level 0: 64 i-tiles (64 rows) x 128 j-tiles (32 cols)
    gram_loss_mma<64, 3><<<dim3(128, 64), 256, smem0>>>(4096, L0_HI, L0_LO, 0);
    // level 1: 16 i-tiles x 32 j-tiles
    gram_loss_mma<128, 3><<<dim3(32, 16), 256, smem1>>>(1024, L1_HI, L1_LO, 1);

    finalize_kernel<<<1, 1>>>(out);
}

// round 8
// speedup vs baseline: 3.7445x; 1.1895x over previous
#include <cuda_runtime.h>
#include <cuda_fp16.h>
#include <cuda_bf16.h>
#include <cstdint>
#include <math.h>

// ============================================================================
// Globals
// ============================================================================

__device__ double g_sum[2];

// fp16 panels, [tb = t*4+b][pos][c] layout (c contiguous):
//  L0: off 0        size 2*4*4096*64 = 2097152
//  L1: off 2097152  size 2*4*1024*128 = 1048576
#define L0_OFF 0
#define L1_OFF 2097152
__device__ __half g_scratch[3145728];

__global__ void init_sums_kernel() { g_sum[0] = 0.0; g_sum[1] = 0.0; }

// ============================================================================
// Pre-convert: fp32 [b][c][pos] -> fp16 panel [tb][pos][C]
// ============================================================================
template <int C>
__global__ void __launch_bounds__(256)
convert_kernel(const float* __restrict__ f1, const float* __restrict__ f2,
               int HW, int off)
{
    __shared__ float tile[C * 65];  // [c][pos0..63], padded
    const int t = blockIdx.z, b = blockIdx.y;
    const int pos0 = blockIdx.x * 64;
    const float* src = (t ? f2 : f1) + (size_t)b * C * HW;

    for (int idx = threadIdx.x; idx < C * 64; idx += 256) {
        int c = idx >> 6, p = idx & 63;
        tile[c * 65 + p] = src[(size_t)c * HW + pos0 + p];
    }
    __syncthreads();

    __half* o = g_scratch + off + ((size_t)(t * 4 + b) * HW + pos0) * C;
    constexpr int CSH = (C == 64) ? 6 : 7;
    for (int idx = threadIdx.x; idx < 64 * C; idx += 256) {
        int p = idx >> CSH, c = idx & (C - 1);
        o[(size_t)p * C + c] = __float2half(tile[c * 65 + p]);
    }
}

// ============================================================================
// PTX helpers (sm_80+ vocabulary only -> safe for plain sm_100 ptxas target)
// ============================================================================

__device__ __forceinline__ uint32_t smem_to_u32(const void* p) {
    uint32_t a;
    asm("{ .reg .u64 t; cvta.to.shared.u64 t, %1; cvt.u32.u64 %0, t; }"
        : "=r"(a) : "l"(p));
    return a;
}

__device__ __forceinline__ void ldmatrix_x4(uint32_t* r, uint32_t addr) {
    asm volatile(
        "ldmatrix.sync.aligned.m8n8.x4.shared.b16 {%0,%1,%2,%3}, [%4];"
        : "=r"(r[0]), "=r"(r[1]), "=r"(r[2]), "=r"(r[3]) : "r"(addr));
}

__device__ __forceinline__ void mma_16816(float* d, const uint32_t* a,
                                          const uint32_t* b) {
    asm volatile(
        "mma.sync.aligned.m16n8k16.row.col.f32.f16.f16.f32 "
        "{%0,%1,%2,%3}, {%4,%5,%6,%7}, {%8,%9}, {%0,%1,%2,%3};"
        : "+f"(d[0]), "+f"(d[1]), "+f"(d[2]), "+f"(d[3])
        : "r"(a[0]), "r"(a[1]), "r"(a[2]), "r"(a[3]), "r"(b[0]), "r"(b[1]));
}

__device__ __forceinline__ void cp_async16(uint32_t saddr, const void* gaddr) {
    asm volatile("cp.async.cg.shared.global [%0], [%1], 16;"
                 :: "r"(saddr), "l"(gaddr));
}
#define CP_COMMIT() asm volatile("cp.async.commit_group;" ::: "memory")
#define CP_WAIT(n)  asm volatile("cp.async.wait_group %0;" :: "n"(n) : "memory")

// ============================================================================
// Fused Gram (mma.sync fp16) + two-phase batch-softmax + |diff|.
// Block: 64(i) x 32(j), 8 warps (4x2), warp 16x16.
// Stage = A | B.  aff1 stored as packed bf16x2.
// ============================================================================
template <int C, int NSTAGES>
__global__ void __launch_bounds__(256, 2)
gram_loss_mma(int HW, int off, int level)
{
    const int ti = blockIdx.y, tj = blockIdx.x;
    if (tj < 2 * ti) return;  // tile entirely below diagonal

    constexpr int NCH = C / 8;                 // 16B chunks per row
    constexpr int A_TILE = C * 128;            // 64 rows, bytes
    constexpr int B_TILE = C * 64;             // 32 rows, bytes
    constexpr int STAGE_B = A_TILE + B_TILE;
    constexpr int KSTEPS = C / 16;

    extern __shared__ char smem[];
    const uint32_t sb = smem_to_u32(smem);
    __nv_bfloat162* aff = (__nv_bfloat162*)(smem + NSTAGES * STAGE_B);  // [s*2+p][tid]

    const int tid = threadIdx.x, wid = tid >> 5, lid = tid & 31;
    const int wrow = wid & 3, wcol = wid >> 2;
    const int i0 = ti * 64, j0 = tj * 32;

    const size_t HWC = (size_t)HW * C;
    auto load_stage = [&](int combo, int stage) {
        const size_t pbase = (size_t)combo * HWC;
        const uint32_t stb = sb + stage * STAGE_B;
        {   // A: 64 rows at i0
            const __half* s = g_scratch + off + pbase + (size_t)i0 * C;
            #pragma unroll
            for (int p = 0; p < (64 * NCH) / 256; ++p) {
                int v = p * 256 + tid;
                int row = v / NCH, kcq = v % NCH;
                cp_async16(stb + (kcq >> 3) * 8192 + row * 128 +
                               (((kcq & 7) ^ (row & 7)) << 4),
                           s + (size_t)row * C + kcq * 8);
            }
        }
        {   // B: 32 rows at j0
            const __half* s = g_scratch + off + pbase + (size_t)j0 * C;
            const uint32_t dst = stb + A_TILE;
            #pragma unroll
            for (int p = 0; p < (32 * NCH) / 256; ++p) {
                int v = p * 256 + tid;
                int row = v / NCH, kcq = v % NCH;
                cp_async16(dst + (kcq >> 3) * 4096 + row * 128 +
                               (((kcq & 7) ^ (row & 7)) << 4),
                           s + (size_t)row * C + kcq * 8);
            }
        }
    };

    // ---- per-lane ldmatrix addressing (stage-invariant) ----
    const int mat = lid >> 3, lrow = lid & 7;
    const int a_row = wrow * 16 + ((mat & 1) << 3) + lrow;
    const int a_kh = mat >> 1;
    const int b_row = wcol * 16 + ((mat >> 1) << 3) + lrow;
    const int b_kh = mat & 1;
    const uint32_t a_off = a_row * 128;
    const uint32_t b_off = A_TILE + b_row * 128;
    const int a_r7 = a_row & 7, b_r7 = b_row & 7;

    load_stage(0, 0); CP_COMMIT();
    load_stage(1, 1); CP_COMMIT();

    float acc[4][8];
    float wsum = 0.0f;
    const bool fullabove = (tj >= 2 * ti + 2);
    const int gi = lid >> 2, gj = (lid & 3) << 1;

    #pragma unroll 1
    for (int t = 0; t < 2; ++t) {
        #pragma unroll
        for (int b = 0; b < 4; ++b) {
            const int combo = t * 4 + b;
            if (combo == 7) { CP_WAIT(0); } else { CP_WAIT(1); }
            __syncthreads();  // combo's stage ready; prior readers done
            if (combo + 2 < 8) {
                load_stage(combo + 2, (combo + 2) % NSTAGES);
                CP_COMMIT();
            }

            const uint32_t stb = sb + (combo % NSTAGES) * STAGE_B;
            const uint32_t a_t = stb + a_off;
            const uint32_t b_t = stb + b_off;
            #pragma unroll
            for (int s = 0; s < 8; ++s) acc[b][s] = 0.0f;

            #pragma unroll
            for (int ks = 0; ks < KSTEPS; ++ks) {
                const int kb = ks >> 2, kc = (ks & 3) * 2;
                uint32_t a[4], bb[4];
                ldmatrix_x4(a,  a_t + kb * 8192 + (((kc + a_kh) ^ a_r7) << 4));
                ldmatrix_x4(bb, b_t + kb * 4096 + (((kc + b_kh) ^ b_r7) << 4));
                mma_16816(acc[b] + 0, a, bb + 0);   // n 0-7
                mma_16816(acc[b] + 4, a, bb + 2);   // n 8-15
            }
        }

        // ---- per-phase epilogue ----
        if (t == 0) {
            // softmax over batch of tensor 1 -> aff smem (packed bf16x2)
            #pragma unroll
            for (int s = 0; s < 8; ++s) {
                float m1 = fmaxf(fmaxf(acc[0][s], acc[1][s]),
                                 fmaxf(acc[2][s], acc[3][s]));
                float e[4], sum = 0.0f;
                #pragma unroll
                for (int b2 = 0; b2 < 4; ++b2) {
                    e[b2] = __expf(acc[b2][s] - m1); sum += e[b2];
                }
                const float inv = __frcp_rn(sum);
                aff[(s * 2 + 0) * 256 + tid] =
                    __floats2bfloat162_rn(e[0] * inv, e[1] * inv);
                aff[(s * 2 + 1) * 256 + tid] =
                    __floats2bfloat162_rn(e[2] * inv, e[3] * inv);
            }
        } else if (fullabove) {
            // fast path: every element weight 2, no index math
            #pragma unroll
            for (int s = 0; s < 8; ++s) {
                float m2 = fmaxf(fmaxf(acc[0][s], acc[1][s]),
                                 fmaxf(acc[2][s], acc[3][s]));
                float e[4], sum = 0.0f;
                #pragma unroll
                for (int b2 = 0; b2 < 4; ++b2) {
                    e[b2] = __expf(acc[b2][s] - m2); sum += e[b2];
                }
                const float inv = __frcp_rn(sum);
                const float2 a01 = __bfloat1622float2(aff[(s * 2 + 0) * 256 + tid]);
                const float2 a23 = __bfloat1622float2(aff[(s * 2 + 1) * 256 + tid]);
                wsum += fabsf(a01.x - e[0] * inv) + fabsf(a01.y - e[1] * inv)
                      + fabsf(a23.x - e[2] * inv) + fabsf(a23.y - e[3] * inv);
            }
        } else {
            #pragma unroll
            for (int s = 0; s < 8; ++s) {
                const int nb = s >> 2, q = s & 3;
                const int i = i0 + wrow * 16 + gi + ((q & 2) << 2);
                const int j = j0 + wcol * 16 + nb * 8 + gj + (q & 1);
                const float w = (j > i) ? 2.0f : ((j == i) ? 1.0f : 0.0f);
                float m2 = fmaxf(fmaxf(acc[0][s], acc[1][s]),
                                 fmaxf(acc[2][s], acc[3][s]));
                float e[4], sum = 0.0f;
                #pragma unroll
                for (int b2 = 0; b2 < 4; ++b2) {
                    e[b2] = __expf(acc[b2][s] - m2); sum += e[b2];
                }
                const float inv = __frcp_rn(sum);
                const float2 a01 = __bfloat1622float2(aff[(s * 2 + 0) * 256 + tid]);
                const float2 a23 = __bfloat1622float2(aff[(s * 2 + 1) * 256 + tid]);
                float d = fabsf(a01.x - e[0] * inv) + fabsf(a01.y - e[1] * inv)
                        + fabsf(a23.x - e[2] * inv) + fabsf(a23.y - e[3] * inv);
                wsum += w * d;
            }
        }
    }

    // ---- reduce: warp shfl -> smem -> single atomic ----
    if (fullabove) wsum *= 2.0f;
    #pragma unroll
    for (int s2 = 16; s2; s2 >>= 1) wsum += __shfl_xor_sync(0xFFFFFFFFu, wsum, s2);
    __syncthreads();             // all stage/aff reads done; reuse smem front
    float* wsums = (float*)smem;
    if (lid == 0) wsums[wid] = wsum;
    __syncthreads();
    if (tid == 0) {
        float tt = 0.0f;
        #pragma unroll
        for (int wq = 0; wq < 8; ++wq) tt += wsums[wq];
        atomicAdd(&g_sum[level], (double)tt);
    }
}

__global__ void finalize_kernel(float* out) {
    const double n0 = 4.0 * 4096.0 * 4096.0;
    const double n1 = 4.0 * 1024.0 * 1024.0;
    out[0] = (float)((g_sum[0] / n0 + g_sum[1] / n1) * 0.5);
}

// ============================================================================
// Launch
// ============================================================================
extern "C" void kernel_launch(void* const* d_in, const int* in_sizes, int n_in,
                              void* d_out, int out_size)
{
    const float* fea1_0 = (const float*)d_in[0];  // (4, 64, 64, 64)
    const float* fea1_1 = (const float*)d_in[1];  // (4, 128, 32, 32)
    const float* fea2_0 = (const float*)d_in[2];
    const float* fea2_1 = (const float*)d_in[3];
    float* out = (float*)d_out;

    // smem: NSTAGES * stage + 16KB bf16 aff buffer
    const int smem0 = 3 * 12288 + 16384;    // C=64  -> 52 KB, 2 CTAs/SM
    const int smem1 = 3 * 24576 + 16384;    // C=128 -> 88 KB, 2 CTAs/SM
    cudaFuncSetAttribute(gram_loss_mma<64, 3>,
                         cudaFuncAttributeMaxDynamicSharedMemorySize, smem0);
    cudaFuncSetAttribute(gram_loss_mma<128, 3>,
                         cudaFuncAttributeMaxDynamicSharedMemorySize, smem1);

    init_sums_kernel<<<1, 1>>>();

    convert_kernel<64><<<dim3(64, 4, 2), 256>>>(fea1_0, fea2_0, 4096, L0_OFF);
    convert_kernel<128><<<dim3(16, 4, 2), 256>>>(fea1_1, fea2_1, 1024, L1_OFF);

    // level 0: 64 i-tiles (64 rows) x 128 j-tiles (32 cols)
    gram_loss_mma<64, 3><<<dim3(128, 64), 256, smem0>>>(4096, L0_OFF, 0);
    // level 1: 16 i-tiles x 32 j-tiles
    gram_loss_mma<128, 3><<<dim3(32, 16), 256, smem1>>>(1024, L1_OFF, 1);

    finalize_kernel<<<1, 1>>>(out);
}

// round 10
// speedup vs baseline: 4.3412x; 1.1593x over previous
#include <cuda_runtime.h>
#include <cuda_fp16.h>
#include <cuda_bf16.h>
#include <cstdint>
#include <math.h>

// ============================================================================
// Globals
// ============================================================================

__device__ double g_sum[2];

// fp16 panels, [tb = t*4+b][pos][c] layout (c contiguous):
#define L0_OFF 0
#define L1_OFF 2097152
__device__ __half g_scratch[3145728];

__global__ void init_sums_kernel() { g_sum[0] = 0.0; g_sum[1] = 0.0; }

// ============================================================================
// Pre-convert: fp32 [b][c][pos] -> fp16 panel [tb][pos][C]
// ============================================================================
template <int C>
__global__ void __launch_bounds__(256)
convert_kernel(const float* __restrict__ f1, const float* __restrict__ f2,
               int HW, int off)
{
    __shared__ float tile[C * 65];  // [c][pos0..63], padded
    const int t = blockIdx.z, b = blockIdx.y;
    const int pos0 = blockIdx.x * 64;
    const float* src = (t ? f2 : f1) + (size_t)b * C * HW;

    for (int idx = threadIdx.x; idx < C * 64; idx += 256) {
        int c = idx >> 6, p = idx & 63;
        tile[c * 65 + p] = src[(size_t)c * HW + pos0 + p];
    }
    __syncthreads();

    __half* o = g_scratch + off + ((size_t)(t * 4 + b) * HW + pos0) * C;
    constexpr int CSH = (C == 64) ? 6 : 7;
    for (int idx = threadIdx.x; idx < 64 * C; idx += 256) {
        int p = idx >> CSH, c = idx & (C - 1);
        o[(size_t)p * C + c] = __float2half(tile[c * 65 + p]);
    }
}

// ============================================================================
// PTX helpers (sm_80+ vocabulary only)
// ============================================================================

__device__ __forceinline__ uint32_t smem_to_u32(const void* p) {
    uint32_t a;
    asm("{ .reg .u64 t; cvta.to.shared.u64 t, %1; cvt.u32.u64 %0, t; }"
        : "=r"(a) : "l"(p));
    return a;
}

__device__ __forceinline__ void ldmatrix_x4(uint32_t* r, uint32_t addr) {
    asm volatile(
        "ldmatrix.sync.aligned.m8n8.x4.shared.b16 {%0,%1,%2,%3}, [%4];"
        : "=r"(r[0]), "=r"(r[1]), "=r"(r[2]), "=r"(r[3]) : "r"(addr));
}

__device__ __forceinline__ void mma_16816(float* d, const uint32_t* a,
                                          const uint32_t* b) {
    asm volatile(
        "mma.sync.aligned.m16n8k16.row.col.f32.f16.f16.f32 "
        "{%0,%1,%2,%3}, {%4,%5,%6,%7}, {%8,%9}, {%0,%1,%2,%3};"
        : "+f"(d[0]), "+f"(d[1]), "+f"(d[2]), "+f"(d[3])
        : "r"(a[0]), "r"(a[1]), "r"(a[2]), "r"(a[3]), "r"(b[0]), "r"(b[1]));
}

__device__ __forceinline__ void cp_async16(uint32_t saddr, const void* gaddr) {
    asm volatile("cp.async.cg.shared.global [%0], [%1], 16;"
                 :: "r"(saddr), "l"(gaddr));
}
#define CP_COMMIT() asm volatile("cp.async.commit_group;" ::: "memory")
#define CP_WAIT(n)  asm volatile("cp.async.wait_group %0;" :: "n"(n) : "memory")

// ============================================================================
// Fused Gram (mma.sync fp16) + two-phase batch-softmax + |diff|.
// Block: 64(i) x 64(j) tile, triangular 1-D grid (tj >= ti).
// 8 warps (4 row x 2 col), warp = 16m x 32n.  A/B tiles share one layout.
// ============================================================================
template <int C, int NSTAGES>
__global__ void __launch_bounds__(256, 2)
gram_loss_mma(int HW, int off, int level)
{
    // ---- triangular decode: blockIdx.x -> (ti, tj), tj >= ti ----
    const int k = blockIdx.x;
    int a = (int)((sqrtf(8.0f * k + 1.0f) - 1.0f) * 0.5f);
    while ((a + 1) * (a + 2) / 2 <= k) ++a;
    while (a * (a + 1) / 2 > k) --a;
    const int ti = k - a * (a + 1) / 2;   // 0..a
    const int tj = a;                     // tj >= ti

    constexpr int NCH = C / 8;                 // 16B chunks per row
    constexpr int TILE_B = (C / 64) * 8192;    // 64 rows x 2C bytes
    constexpr int STAGE_B = 2 * TILE_B;        // A | B
    constexpr int KSTEPS = C / 16;

    extern __shared__ char smem[];
    const uint32_t sb = smem_to_u32(smem);
    __nv_bfloat162* aff = (__nv_bfloat162*)(smem + NSTAGES * STAGE_B);  // 32 KB

    const int tid = threadIdx.x, wid = tid >> 5, lid = tid & 31;
    const int wrow = wid & 3, wcol = wid >> 2;
    const int i0 = ti * 64, j0 = tj * 64;

    const size_t HWC = (size_t)HW * C;
    auto load_stage = [&](int combo, int stage) {
        const size_t pbase = (size_t)combo * HWC;
        const uint32_t stb = sb + stage * STAGE_B;
        const __half* sA = g_scratch + off + pbase + (size_t)i0 * C;
        const __half* sB = g_scratch + off + pbase + (size_t)j0 * C;
        #pragma unroll
        for (int p = 0; p < (64 * NCH) / 256; ++p) {
            int v = p * 256 + tid;
            int row = v / NCH, kcq = v % NCH;
            uint32_t o = (kcq >> 3) * 8192 + row * 128 +
                         (((kcq & 7) ^ (row & 7)) << 4);
            const size_t go = (size_t)row * C + kcq * 8;
            cp_async16(stb + o, sA + go);
            cp_async16(stb + TILE_B + o, sB + go);
        }
    };

    // ---- per-lane ldmatrix addressing (stage-invariant) ----
    const int mat = lid >> 3, lrow = lid & 7;
    const int a_row = wrow * 16 + ((mat & 1) << 3) + lrow;
    const int a_kh = mat >> 1;
    const int b_row0 = wcol * 32 + ((mat >> 1) << 3) + lrow;
    const int b_row1 = b_row0 + 16;
    const int b_kh = mat & 1;
    const uint32_t a_off  = a_row * 128;
    const uint32_t b_off0 = TILE_B + b_row0 * 128;
    const uint32_t b_off1 = TILE_B + b_row1 * 128;
    const int a_r7 = a_row & 7, b_r70 = b_row0 & 7, b_r71 = b_row1 & 7;

    load_stage(0, 0); CP_COMMIT();
    load_stage(1, 1); CP_COMMIT();

    float acc[4][16];
    float wsum = 0.0f;
    const bool fullabove = (tj > ti);
    const int gi = lid >> 2, gj = (lid & 3) << 1;

    #pragma unroll 1
    for (int t = 0; t < 2; ++t) {
        #pragma unroll
        for (int b = 0; b < 4; ++b) {
            const int combo = t * 4 + b;
            if (combo == 7) { CP_WAIT(0); } else { CP_WAIT(1); }
            __syncthreads();  // combo's stage ready; prior readers done
            if (combo + 2 < 8) {
                load_stage(combo + 2, (combo + 2) % NSTAGES);
                CP_COMMIT();
            }

            const uint32_t stb = sb + (combo % NSTAGES) * STAGE_B;
            #pragma unroll
            for (int s = 0; s < 16; ++s) acc[b][s] = 0.0f;

            #pragma unroll
            for (int ks = 0; ks < KSTEPS; ++ks) {
                const int kb = ks >> 2, kc = (ks & 3) * 2;
                uint32_t af[4], b0[4], b1[4];
                ldmatrix_x4(af, stb + a_off  + kb * 8192 +
                                (((kc + a_kh) ^ a_r7)  << 4));
                ldmatrix_x4(b0, stb + b_off0 + kb * 8192 +
                                (((kc + b_kh) ^ b_r70) << 4));
                ldmatrix_x4(b1, stb + b_off1 + kb * 8192 +
                                (((kc + b_kh) ^ b_r71) << 4));
                mma_16816(acc[b] + 0,  af, b0 + 0);   // h0 n0-7
                mma_16816(acc[b] + 4,  af, b0 + 2);   // h0 n8-15
                mma_16816(acc[b] + 8,  af, b1 + 0);   // h1 n0-7
                mma_16816(acc[b] + 12, af, b1 + 2);   // h1 n8-15
            }
        }

        // ---- per-phase epilogue (max-subtracted softmax: diag entries ~C
        //      would overflow expf without it) ----
        if (t == 0) {
            #pragma unroll
            for (int s = 0; s < 16; ++s) {
                const float m1 = fmaxf(fmaxf(acc[0][s], acc[1][s]),
                                       fmaxf(acc[2][s], acc[3][s]));
                float e[4], sum = 0.0f;
                #pragma unroll
                for (int b2 = 0; b2 < 4; ++b2) {
                    e[b2] = __expf(acc[b2][s] - m1); sum += e[b2];
                }
                const float inv = __frcp_rn(sum);
                aff[(s * 2 + 0) * 256 + tid] =
                    __floats2bfloat162_rn(e[0] * inv, e[1] * inv);
                aff[(s * 2 + 1) * 256 + tid] =
                    __floats2bfloat162_rn(e[2] * inv, e[3] * inv);
            }
        } else if (fullabove) {
            #pragma unroll
            for (int s = 0; s < 16; ++s) {
                const float m2 = fmaxf(fmaxf(acc[0][s], acc[1][s]),
                                       fmaxf(acc[2][s], acc[3][s]));
                float e[4], sum = 0.0f;
                #pragma unroll
                for (int b2 = 0; b2 < 4; ++b2) {
                    e[b2] = __expf(acc[b2][s] - m2); sum += e[b2];
                }
                const float inv = __frcp_rn(sum);
                const float2 a01 = __bfloat1622float2(aff[(s * 2 + 0) * 256 + tid]);
                const float2 a23 = __bfloat1622float2(aff[(s * 2 + 1) * 256 + tid]);
                wsum += fabsf(a01.x - e[0] * inv) + fabsf(a01.y - e[1] * inv)
                      + fabsf(a23.x - e[2] * inv) + fabsf(a23.y - e[3] * inv);
            }
        } else {
            // diagonal tile: per-element triangle weights
            #pragma unroll
            for (int s = 0; s < 16; ++s) {
                const int h = s >> 3, r = s & 7, nb = r >> 2, q = r & 3;
                const int i = i0 + wrow * 16 + gi + ((q & 2) << 2);
                const int j = j0 + wcol * 32 + h * 16 + nb * 8 + gj + (q & 1);
                const float w = (j > i) ? 2.0f : ((j == i) ? 1.0f : 0.0f);
                const float m2 = fmaxf(fmaxf(acc[0][s], acc[1][s]),
                                       fmaxf(acc[2][s], acc[3][s]));
                float e[4], sum = 0.0f;
                #pragma unroll
                for (int b2 = 0; b2 < 4; ++b2) {
                    e[b2] = __expf(acc[b2][s] - m2); sum += e[b2];
                }
                const float inv = __frcp_rn(sum);
                const float2 a01 = __bfloat1622float2(aff[(s * 2 + 0) * 256 + tid]);
                const float2 a23 = __bfloat1622float2(aff[(s * 2 + 1) * 256 + tid]);
                float d = fabsf(a01.x - e[0] * inv) + fabsf(a01.y - e[1] * inv)
                        + fabsf(a23.x - e[2] * inv) + fabsf(a23.y - e[3] * inv);
                wsum += w * d;
            }
        }
    }

    // ---- reduce: warp shfl -> smem -> single atomic ----
    if (fullabove) wsum *= 2.0f;
    #pragma unroll
    for (int s2 = 16; s2; s2 >>= 1) wsum += __shfl_xor_sync(0xFFFFFFFFu, wsum, s2);
    __syncthreads();
    float* wsums = (float*)smem;
    if (lid == 0) wsums[wid] = wsum;
    __syncthreads();
    if (tid == 0) {
        float tt = 0.0f;
        #pragma unroll
        for (int wq = 0; wq < 8; ++wq) tt += wsums[wq];
        atomicAdd(&g_sum[level], (double)tt);
    }
}

__global__ void finalize_kernel(float* out) {
    const double n0 = 4.0 * 4096.0 * 4096.0;
    const double n1 = 4.0 * 1024.0 * 1024.0;
    out[0] = (float)((g_sum[0] / n0 + g_sum[1] / n1) * 0.5);
}

// ============================================================================
// Launch
// ============================================================================
extern "C" void kernel_launch(void* const* d_in, const int* in_sizes, int n_in,
                              void* d_out, int out_size)
{
    const float* fea1_0 = (const float*)d_in[0];  // (4, 64, 64, 64)
    const float* fea1_1 = (const float*)d_in[1];  // (4, 128, 32, 32)
    const float* fea2_0 = (const float*)d_in[2];
    const float* fea2_1 = (const float*)d_in[3];
    float* out = (float*)d_out;

    // smem: NSTAGES * stage + 32KB bf16 aff buffer
    const int smem0 = 3 * 16384 + 32768;    // C=64  -> 80 KB,  2 CTAs/SM
    const int smem1 = 3 * 32768 + 32768;    // C=128 -> 128 KB, 1 CTA/SM (1 wave)
    cudaFuncSetAttribute(gram_loss_mma<64, 3>,
                         cudaFuncAttributeMaxDynamicSharedMemorySize, smem0);
    cudaFuncSetAttribute(gram_loss_mma<128, 3>,
                         cudaFuncAttributeMaxDynamicSharedMemorySize, smem1);

    init_sums_kernel<<<1, 1>>>();

    convert_kernel<64><<<dim3(64, 4, 2), 256>>>(fea1_0, fea2_0, 4096, L0_OFF);
    convert_kernel<128><<<dim3(16, 4, 2), 256>>>(fea1_1, fea2_1, 1024, L1_OFF);

    // triangular grids: T*(T+1)/2 blocks of 64x64
    gram_loss_mma<64, 3><<<64 * 65 / 2, 256, smem0>>>(4096, L0_OFF, 0);   // 2080
    gram_loss_mma<128, 3><<<16 * 17 / 2, 256, smem1>>>(1024, L1_OFF, 1);  // 136

    finalize_kernel<<<1, 1>>>(out);
}

// round 11
// speedup vs baseline: 4.4903x; 1.0344x over previous
#include <cuda_runtime.h>
#include <cuda_fp16.h>
#include <cstdint>
#include <math.h>

// ============================================================================
// Globals
// ============================================================================

__device__ double g_sum[2];

// fp16 panels, [tb = t*4+b][pos][c] layout (c contiguous):
#define L0_OFF 0
#define L1_OFF 2097152
__device__ __half g_scratch[3145728];

__global__ void init_sums_kernel() { g_sum[0] = 0.0; g_sum[1] = 0.0; }

// ============================================================================
// Pre-convert: fp32 [b][c][pos] -> fp16 panel [tb][pos][C]
// ============================================================================
template <int C>
__global__ void __launch_bounds__(256)
convert_kernel(const float* __restrict__ f1, const float* __restrict__ f2,
               int HW, int off)
{
    __shared__ float tile[C * 65];  // [c][pos0..63], padded
    const int t = blockIdx.z, b = blockIdx.y;
    const int pos0 = blockIdx.x * 64;
    const float* src = (t ? f2 : f1) + (size_t)b * C * HW;

    for (int idx = threadIdx.x; idx < C * 64; idx += 256) {
        int c = idx >> 6, p = idx & 63;
        tile[c * 65 + p] = src[(size_t)c * HW + pos0 + p];
    }
    __syncthreads();

    __half* o = g_scratch + off + ((size_t)(t * 4 + b) * HW + pos0) * C;
    constexpr int CSH = (C == 64) ? 6 : 7;
    for (int idx = threadIdx.x; idx < 64 * C; idx += 256) {
        int p = idx >> CSH, c = idx & (C - 1);
        o[(size_t)p * C + c] = __float2half(tile[c * 65 + p]);
    }
}

// ============================================================================
// PTX helpers (sm_80+ vocabulary only)
// ============================================================================

__device__ __forceinline__ uint32_t smem_to_u32(const void* p) {
    uint32_t a;
    asm("{ .reg .u64 t; cvta.to.shared.u64 t, %1; cvt.u32.u64 %0, t; }"
        : "=r"(a) : "l"(p));
    return a;
}

__device__ __forceinline__ void ldmatrix_x4(uint32_t* r, uint32_t addr) {
    asm volatile(
        "ldmatrix.sync.aligned.m8n8.x4.shared.b16 {%0,%1,%2,%3}, [%4];"
        : "=r"(r[0]), "=r"(r[1]), "=r"(r[2]), "=r"(r[3]) : "r"(addr));
}

// fp16-accumulate MMA: D (2 regs of half2) += A @ B^T
__device__ __forceinline__ void mma_16816_h(uint32_t* d, const uint32_t* a,
                                            const uint32_t* b) {
    asm volatile(
        "mma.sync.aligned.m16n8k16.row.col.f16.f16.f16.f16 "
        "{%0,%1}, {%2,%3,%4,%5}, {%6,%7}, {%0,%1};"
        : "+r"(d[0]), "+r"(d[1])
        : "r"(a[0]), "r"(a[1]), "r"(a[2]), "r"(a[3]), "r"(b[0]), "r"(b[1]));
}

__device__ __forceinline__ void cp_async16(uint32_t saddr, const void* gaddr) {
    asm volatile("cp.async.cg.shared.global [%0], [%1], 16;"
                 :: "r"(saddr), "l"(gaddr));
}
#define CP_COMMIT() asm volatile("cp.async.commit_group;" ::: "memory")
#define CP_WAIT(n)  asm volatile("cp.async.wait_group %0;" :: "n"(n) : "memory")

__device__ __forceinline__ __half2 u2h(uint32_t v) {
    return *reinterpret_cast<__half2*>(&v);
}
__device__ __forceinline__ uint32_t h2u(__half2 v) {
    return *reinterpret_cast<uint32_t*>(&v);
}

// ============================================================================
// Fused Gram (mma.sync fp16 acc) + two-phase half2 batch-softmax + |diff|.
// Block: 64(i) x 64(j) tile, triangular 1-D grid (tj >= ti).
// 8 warps (4 row x 2 col), warp = 16m x 32n.  acc = 8 half2 regs per batch.
// ============================================================================
template <int C, int NSTAGES>
__global__ void __launch_bounds__(256, 2)
gram_loss_mma(int HW, int off, int level)
{
    // ---- triangular decode: blockIdx.x -> (ti, tj), tj >= ti ----
    const int k = blockIdx.x;
    int a = (int)((sqrtf(8.0f * k + 1.0f) - 1.0f) * 0.5f);
    while ((a + 1) * (a + 2) / 2 <= k) ++a;
    while (a * (a + 1) / 2 > k) --a;
    const int ti = k - a * (a + 1) / 2;   // 0..a
    const int tj = a;                     // tj >= ti

    constexpr int NCH = C / 8;                 // 16B chunks per row
    constexpr int TILE_B = (C / 64) * 8192;    // 64 rows x 2C bytes
    constexpr int STAGE_B = 2 * TILE_B;        // A | B
    constexpr int KSTEPS = C / 16;
    constexpr int NLOAD = (64 * NCH) / 256;    // cp.async iters per tile/thread

    extern __shared__ char smem[];
    const uint32_t sb = smem_to_u32(smem);
    uint32_t* aff = (uint32_t*)(smem + NSTAGES * STAGE_B);  // [b*8+r][tid] 32 KB

    const int tid = threadIdx.x, wid = tid >> 5, lid = tid & 31;
    const int wrow = wid & 3, wcol = wid >> 2;
    const int i0 = ti * 64, j0 = tj * 64;

    // ---- precomputed loader offsets (combo/stage-invariant) ----
    uint32_t lo_sm[NLOAD];
    uint32_t lo_gl[NLOAD];
    #pragma unroll
    for (int p = 0; p < NLOAD; ++p) {
        const int v = p * 256 + tid;
        const int row = v / NCH, kcq = v % NCH;
        lo_sm[p] = (kcq >> 3) * 8192 + row * 128 +
                   (((kcq & 7) ^ (row & 7)) << 4);
        lo_gl[p] = row * C + kcq * 8;
    }

    const size_t HWC = (size_t)HW * C;
    auto load_stage = [&](int combo, int stage) {
        const __half* base = g_scratch + off + (size_t)combo * HWC;
        const __half* sA = base + (size_t)i0 * C;
        const __half* sB = base + (size_t)j0 * C;
        const uint32_t stb = sb + stage * STAGE_B;
        #pragma unroll
        for (int p = 0; p < NLOAD; ++p) {
            cp_async16(stb + lo_sm[p], sA + lo_gl[p]);
            cp_async16(stb + TILE_B + lo_sm[p], sB + lo_gl[p]);
        }
    };

    // ---- per-lane ldmatrix addressing (stage-invariant) ----
    const int mat = lid >> 3, lrow = lid & 7;
    const int a_row = wrow * 16 + ((mat & 1) << 3) + lrow;
    const int a_kh = mat >> 1;
    const int b_row0 = wcol * 32 + ((mat >> 1) << 3) + lrow;
    const int b_row1 = b_row0 + 16;
    const int b_kh = mat & 1;
    const uint32_t a_off  = a_row * 128;
    const uint32_t b_off0 = TILE_B + b_row0 * 128;
    const uint32_t b_off1 = TILE_B + b_row1 * 128;
    const int a_r7 = a_row & 7, b_r70 = b_row0 & 7, b_r71 = b_row1 & 7;

    load_stage(0, 0); CP_COMMIT();
    load_stage(1, 1); CP_COMMIT();

    // acc[b][r]: r = mi*2 + dreg; mi: 0=(h0,nb0) 1=(h0,nb1) 2=(h1,nb0) 3=(h1,nb1)
    // dreg 0 -> row gi, 1 -> row gi+8; each reg = half2 over cols (j, j+1)
    uint32_t acc[4][8];
    float wsum = 0.0f;
    const bool fullabove = (tj > ti);
    const int gi = lid >> 2, gj = (lid & 3) << 1;

    #pragma unroll 1
    for (int t = 0; t < 2; ++t) {
        #pragma unroll
        for (int b = 0; b < 4; ++b) {
            const int combo = t * 4 + b;
            if (combo == 7) { CP_WAIT(0); } else { CP_WAIT(1); }
            __syncthreads();  // combo's stage ready; prior readers done
            if (combo + 2 < 8) {
                load_stage(combo + 2, (combo + 2) % NSTAGES);
                CP_COMMIT();
            }

            const uint32_t stb = sb + (combo % NSTAGES) * STAGE_B;
            #pragma unroll
            for (int s = 0; s < 8; ++s) acc[b][s] = 0u;

            #pragma unroll
            for (int ks = 0; ks < KSTEPS; ++ks) {
                const int kb = ks >> 2, kc = (ks & 3) * 2;
                uint32_t af[4], b0[4], b1[4];
                ldmatrix_x4(af, stb + a_off  + kb * 8192 +
                                (((kc + a_kh) ^ a_r7)  << 4));
                ldmatrix_x4(b0, stb + b_off0 + kb * 8192 +
                                (((kc + b_kh) ^ b_r70) << 4));
                ldmatrix_x4(b1, stb + b_off1 + kb * 8192 +
                                (((kc + b_kh) ^ b_r71) << 4));
                mma_16816_h(acc[b] + 0, af, b0 + 0);   // h0 nb0 -> r0,r1
                mma_16816_h(acc[b] + 2, af, b0 + 2);   // h0 nb1 -> r2,r3
                mma_16816_h(acc[b] + 4, af, b1 + 0);   // h1 nb0 -> r4,r5
                mma_16816_h(acc[b] + 6, af, b1 + 2);   // h1 nb1 -> r6,r7
            }
        }

        // ---- per-phase half2 epilogue (max-subtracted softmax) ----
        #pragma unroll
        for (int r = 0; r < 8; ++r) {
            const __half2 A0 = u2h(acc[0][r]), A1 = u2h(acc[1][r]);
            const __half2 A2 = u2h(acc[2][r]), A3 = u2h(acc[3][r]);
            const __half2 m = __hmax2(__hmax2(A0, A1), __hmax2(A2, A3));
            const __half2 e0 = h2exp(__hsub2(A0, m));
            const __half2 e1 = h2exp(__hsub2(A1, m));
            const __half2 e2 = h2exp(__hsub2(A2, m));
            const __half2 e3 = h2exp(__hsub2(A3, m));
            const __half2 sum = __hadd2(__hadd2(e0, e1), __hadd2(e2, e3));
            const __half2 inv = h2rcp(sum);
            const __half2 p0 = __hmul2(e0, inv), p1 = __hmul2(e1, inv);
            const __half2 p2 = __hmul2(e2, inv), p3 = __hmul2(e3, inv);

            if (t == 0) {
                aff[(0 * 8 + r) * 256 + tid] = h2u(p0);
                aff[(1 * 8 + r) * 256 + tid] = h2u(p1);
                aff[(2 * 8 + r) * 256 + tid] = h2u(p2);
                aff[(3 * 8 + r) * 256 + tid] = h2u(p3);
            } else {
                __half2 d = __habs2(__hsub2(u2h(aff[(0*8+r)*256 + tid]), p0));
                d = __hadd2(d, __habs2(__hsub2(u2h(aff[(1*8+r)*256 + tid]), p1)));
                d = __hadd2(d, __habs2(__hsub2(u2h(aff[(2*8+r)*256 + tid]), p2)));
                d = __hadd2(d, __habs2(__hsub2(u2h(aff[(3*8+r)*256 + tid]), p3)));
                const float2 dd = __half22float2(d);
                if (fullabove) {
                    wsum += dd.x + dd.y;
                } else {
                    const int mi = r >> 1;
                    const int i = i0 + wrow * 16 + gi + ((r & 1) << 3);
                    const int j = j0 + wcol * 32 + ((mi >> 1) << 4)
                                + ((mi & 1) << 3) + gj;
                    const float wlo = (j > i) ? 2.0f : ((j == i) ? 1.0f : 0.0f);
                    const float whi = (j + 1 > i) ? 2.0f : ((j + 1 == i) ? 1.0f : 0.0f);
                    wsum += wlo * dd.x + whi * dd.y;
                }
            }
        }
    }

    // ---- reduce: warp shfl -> smem -> single atomic ----
    if (fullabove) wsum *= 2.0f;
    #pragma unroll
    for (int s2 = 16; s2; s2 >>= 1) wsum += __shfl_xor_sync(0xFFFFFFFFu, wsum, s2);
    __syncthreads();
    float* wsums = (float*)smem;
    if (lid == 0) wsums[wid] = wsum;
    __syncthreads();
    if (tid == 0) {
        float tt = 0.0f;
        #pragma unroll
        for (int wq = 0; wq < 8; ++wq) tt += wsums[wq];
        atomicAdd(&g_sum[level], (double)tt);
    }
}

__global__ void finalize_kernel(float* out) {
    const double n0 = 4.0 * 4096.0 * 4096.0;
    const double n1 = 4.0 * 1024.0 * 1024.0;
    out[0] = (float)((g_sum[0] / n0 + g_sum[1] / n1) * 0.5);
}

// ============================================================================
// Launch
// ============================================================================
extern "C" void kernel_launch(void* const* d_in, const int* in_sizes, int n_in,
                              void* d_out, int out_size)
{
    const float* fea1_0 = (const float*)d_in[0];  // (4, 64, 64, 64)
    const float* fea1_1 = (const float*)d_in[1];  // (4, 128, 32, 32)
    const float* fea2_0 = (const float*)d_in[2];
    const float* fea2_1 = (const float*)d_in[3];
    float* out = (float*)d_out;

    // smem: NSTAGES * stage + 32KB aff buffer
    const int smem0 = 3 * 16384 + 32768;    // C=64  -> 80 KB,  2 CTAs/SM
    const int smem1 = 3 * 32768 + 32768;    // C=128 -> 128 KB, 1 CTA/SM (1 wave)
    cudaFuncSetAttribute(gram_loss_mma<64, 3>,
                         cudaFuncAttributeMaxDynamicSharedMemorySize, smem0);
    cudaFuncSetAttribute(gram_loss_mma<128, 3>,
                         cudaFuncAttributeMaxDynamicSharedMemorySize, smem1);

    init_sums_kernel<<<1, 1>>>();

    convert_kernel<64><<<dim3(64, 4, 2), 256>>>(fea1_0, fea2_0, 4096, L0_OFF);
    convert_kernel<128><<<dim3(16, 4, 2), 256>>>(fea1_1, fea2_1, 1024, L1_OFF);

    // triangular grids: T*(T+1)/2 blocks of 64x64
    gram_loss_mma<64, 3><<<64 * 65 / 2, 256, smem0>>>(4096, L0_OFF, 0);   // 2080
    gram_loss_mma<128, 3><<<16 * 17 / 2, 256, smem1>>>(1024, L1_OFF, 1);  // 136

    finalize_kernel<<<1, 1>>>(out);
}

// round 12
// speedup vs baseline: 4.8760x; 1.0859x over previous
#include <cuda_runtime.h>
#include <cuda_fp16.h>
#include <cstdint>
#include <math.h>

// ============================================================================
// Globals
// ============================================================================

__device__ double g_sum[2];

// fp16 panels (pre-scaled by sqrt(log2e)), [tb = t*4+b][pos][c] layout:
#define L0_OFF 0
#define L1_OFF 2097152
__device__ __half g_scratch[3145728];

__global__ void init_sums_kernel() { g_sum[0] = 0.0; g_sum[1] = 0.0; }

// ============================================================================
// Pre-convert: fp32 [b][c][pos] -> fp16 panel [tb][pos][C], scaled by
// sqrt(log2e) so the Gram matrix arrives pre-multiplied by log2(e) and the
// softmax exp becomes a raw ex2.
// ============================================================================
#define SQRT_LOG2E 1.2011224087f

template <int C>
__global__ void __launch_bounds__(256)
convert_kernel(const float* __restrict__ f1, const float* __restrict__ f2,
               int HW, int off)
{
    __shared__ float tile[C * 65];  // [c][pos0..63], padded
    const int t = blockIdx.z, b = blockIdx.y;
    const int pos0 = blockIdx.x * 64;
    const float* src = (t ? f2 : f1) + (size_t)b * C * HW;

    for (int idx = threadIdx.x; idx < C * 64; idx += 256) {
        int c = idx >> 6, p = idx & 63;
        tile[c * 65 + p] = src[(size_t)c * HW + pos0 + p];
    }
    __syncthreads();

    __half* o = g_scratch + off + ((size_t)(t * 4 + b) * HW + pos0) * C;
    constexpr int CSH = (C == 64) ? 6 : 7;
    for (int idx = threadIdx.x; idx < 64 * C; idx += 256) {
        int p = idx >> CSH, c = idx & (C - 1);
        o[(size_t)p * C + c] = __float2half(tile[c * 65 + p] * SQRT_LOG2E);
    }
}

// ============================================================================
// PTX helpers (sm_80+ vocabulary only)
// ============================================================================

__device__ __forceinline__ uint32_t smem_to_u32(const void* p) {
    uint32_t a;
    asm("{ .reg .u64 t; cvta.to.shared.u64 t, %1; cvt.u32.u64 %0, t; }"
        : "=r"(a) : "l"(p));
    return a;
}

__device__ __forceinline__ void ldmatrix_x4(uint32_t* r, uint32_t addr) {
    asm volatile(
        "ldmatrix.sync.aligned.m8n8.x4.shared.b16 {%0,%1,%2,%3}, [%4];"
        : "=r"(r[0]), "=r"(r[1]), "=r"(r[2]), "=r"(r[3]) : "r"(addr));
}

// fp16-accumulate MMA: D (2 regs of half2) += A @ B^T
__device__ __forceinline__ void mma_16816_h(uint32_t* d, const uint32_t* a,
                                            const uint32_t* b) {
    asm volatile(
        "mma.sync.aligned.m16n8k16.row.col.f16.f16.f16.f16 "
        "{%0,%1}, {%2,%3,%4,%5}, {%6,%7}, {%0,%1};"
        : "+r"(d[0]), "+r"(d[1])
        : "r"(a[0]), "r"(a[1]), "r"(a[2]), "r"(a[3]), "r"(b[0]), "r"(b[1]));
}

__device__ __forceinline__ void cp_async16(uint32_t saddr, const void* gaddr) {
    asm volatile("cp.async.cg.shared.global [%0], [%1], 16;"
                 :: "r"(saddr), "l"(gaddr));
}
#define CP_COMMIT() asm volatile("cp.async.commit_group;" ::: "memory")
#define CP_WAIT(n)  asm volatile("cp.async.wait_group %0;" :: "n"(n) : "memory")

__device__ __forceinline__ __half2 u2h(uint32_t v) {
    return *reinterpret_cast<__half2*>(&v);
}
__device__ __forceinline__ uint32_t h2u(__half2 v) {
    return *reinterpret_cast<uint32_t*>(&v);
}

// single-instruction f16x2 2^x
__device__ __forceinline__ __half2 ex2_h2(__half2 x) {
    uint32_t r, xi = h2u(x);
    asm("ex2.approx.f16x2 %0, %1;" : "=r"(r) : "r"(xi));
    return u2h(r);
}

// fast per-element reciprocal of a half2 via 2x rcp.approx.f32
__device__ __forceinline__ __half2 rcp_h2(__half2 s) {
    float lo = __low2float(s), hi = __high2float(s);
    float rlo, rhi;
    asm("rcp.approx.f32 %0, %1;" : "=f"(rlo) : "f"(lo));
    asm("rcp.approx.f32 %0, %1;" : "=f"(rhi) : "f"(hi));
    return __floats2half2_rn(rlo, rhi);
}

// ============================================================================
// Fused Gram (mma.sync fp16 acc) + two-phase f16x2 batch-softmax + |diff|.
// Block: 64(i) x 64(j) tile, triangular 1-D grid (tj >= ti).
// 8 warps (4 row x 2 col), warp = 16m x 32n.  acc = 8 half2 regs per batch.
// ============================================================================
template <int C, int NSTAGES>
__global__ void __launch_bounds__(256, 2)
gram_loss_mma(int HW, int off, int level)
{
    // ---- triangular decode: blockIdx.x -> (ti, tj), tj >= ti ----
    const int k = blockIdx.x;
    int a = (int)((sqrtf(8.0f * k + 1.0f) - 1.0f) * 0.5f);
    while ((a + 1) * (a + 2) / 2 <= k) ++a;
    while (a * (a + 1) / 2 > k) --a;
    const int ti = k - a * (a + 1) / 2;   // 0..a
    const int tj = a;                     // tj >= ti

    constexpr int NCH = C / 8;                 // 16B chunks per row
    constexpr int TILE_B = (C / 64) * 8192;    // 64 rows x 2C bytes
    constexpr int STAGE_B = 2 * TILE_B;        // A | B
    constexpr int KSTEPS = C / 16;
    constexpr int NLOAD = (64 * NCH) / 256;    // cp.async iters per tile/thread

    extern __shared__ char smem[];
    const uint32_t sb = smem_to_u32(smem);
    uint32_t* aff = (uint32_t*)(smem + NSTAGES * STAGE_B);  // [b*8+r][tid] 32 KB

    const int tid = threadIdx.x, wid = tid >> 5, lid = tid & 31;
    const int wrow = wid & 3, wcol = wid >> 2;
    const int i0 = ti * 64, j0 = tj * 64;

    // ---- precomputed loader offsets (combo/stage-invariant) ----
    uint32_t lo_sm[NLOAD];
    uint32_t lo_gl[NLOAD];
    #pragma unroll
    for (int p = 0; p < NLOAD; ++p) {
        const int v = p * 256 + tid;
        const int row = v / NCH, kcq = v % NCH;
        lo_sm[p] = (kcq >> 3) * 8192 + row * 128 +
                   (((kcq & 7) ^ (row & 7)) << 4);
        lo_gl[p] = row * C + kcq * 8;
    }

    const size_t HWC = (size_t)HW * C;
    auto load_stage = [&](int combo, int stage) {
        const __half* base = g_scratch + off + (size_t)combo * HWC;
        const __half* sA = base + (size_t)i0 * C;
        const __half* sB = base + (size_t)j0 * C;
        const uint32_t stb = sb + stage * STAGE_B;
        #pragma unroll
        for (int p = 0; p < NLOAD; ++p) {
            cp_async16(stb + lo_sm[p], sA + lo_gl[p]);
            cp_async16(stb + TILE_B + lo_sm[p], sB + lo_gl[p]);
        }
    };

    // ---- per-lane ldmatrix addressing (stage-invariant) ----
    const int mat = lid >> 3, lrow = lid & 7;
    const int a_row = wrow * 16 + ((mat & 1) << 3) + lrow;
    const int a_kh = mat >> 1;
    const int b_row0 = wcol * 32 + ((mat >> 1) << 3) + lrow;
    const int b_row1 = b_row0 + 16;
    const int b_kh = mat & 1;
    const uint32_t a_off  = a_row * 128;
    const uint32_t b_off0 = TILE_B + b_row0 * 128;
    const uint32_t b_off1 = TILE_B + b_row1 * 128;
    const int a_r7 = a_row & 7, b_r70 = b_row0 & 7, b_r71 = b_row1 & 7;

    load_stage(0, 0); CP_COMMIT();
    load_stage(1, 1); CP_COMMIT();

    // acc[b][r]: r = mi*2 + dreg; mi: 0=(h0,nb0) 1=(h0,nb1) 2=(h1,nb0) 3=(h1,nb1)
    // dreg 0 -> row gi, 1 -> row gi+8; each reg = half2 over cols (j, j+1)
    uint32_t acc[4][8];
    float wsum = 0.0f;
    const bool fullabove = (tj > ti);
    const int gi = lid >> 2, gj = (lid & 3) << 1;

    #pragma unroll 1
    for (int t = 0; t < 2; ++t) {
        #pragma unroll
        for (int b = 0; b < 4; ++b) {
            const int combo = t * 4 + b;
            if (combo == 7) { CP_WAIT(0); } else { CP_WAIT(1); }
            __syncthreads();  // combo's stage ready; prior readers done
            if (combo + 2 < 8) {
                load_stage(combo + 2, (combo + 2) % NSTAGES);
                CP_COMMIT();
            }

            const uint32_t stb = sb + (combo % NSTAGES) * STAGE_B;
            #pragma unroll
            for (int s = 0; s < 8; ++s) acc[b][s] = 0u;

            #pragma unroll
            for (int ks = 0; ks < KSTEPS; ++ks) {
                const int kb = ks >> 2, kc = (ks & 3) * 2;
                uint32_t af[4], b0[4], b1[4];
                ldmatrix_x4(af, stb + a_off  + kb * 8192 +
                                (((kc + a_kh) ^ a_r7)  << 4));
                ldmatrix_x4(b0, stb + b_off0 + kb * 8192 +
                                (((kc + b_kh) ^ b_r70) << 4));
                ldmatrix_x4(b1, stb + b_off1 + kb * 8192 +
                                (((kc + b_kh) ^ b_r71) << 4));
                mma_16816_h(acc[b] + 0, af, b0 + 0);   // h0 nb0 -> r0,r1
                mma_16816_h(acc[b] + 2, af, b0 + 2);   // h0 nb1 -> r2,r3
                mma_16816_h(acc[b] + 4, af, b1 + 0);   // h1 nb0 -> r4,r5
                mma_16816_h(acc[b] + 6, af, b1 + 2);   // h1 nb1 -> r6,r7
            }
        }

        // ---- per-phase f16x2 epilogue: softmax over batch (base-2, data
        //      pre-scaled by log2e) + |diff| ----
        #pragma unroll
        for (int r = 0; r < 8; ++r) {
            const __half2 A0 = u2h(acc[0][r]), A1 = u2h(acc[1][r]);
            const __half2 A2 = u2h(acc[2][r]), A3 = u2h(acc[3][r]);
            const __half2 m = __hmax2(__hmax2(A0, A1), __hmax2(A2, A3));
            const __half2 e0 = ex2_h2(__hsub2(A0, m));
            const __half2 e1 = ex2_h2(__hsub2(A1, m));
            const __half2 e2 = ex2_h2(__hsub2(A2, m));
            const __half2 e3 = ex2_h2(__hsub2(A3, m));
            const __half2 sum = __hadd2(__hadd2(e0, e1), __hadd2(e2, e3));
            const __half2 inv = rcp_h2(sum);
            const __half2 p0 = __hmul2(e0, inv), p1 = __hmul2(e1, inv);
            const __half2 p2 = __hmul2(e2, inv), p3 = __hmul2(e3, inv);

            if (t == 0) {
                aff[(0 * 8 + r) * 256 + tid] = h2u(p0);
                aff[(1 * 8 + r) * 256 + tid] = h2u(p1);
                aff[(2 * 8 + r) * 256 + tid] = h2u(p2);
                aff[(3 * 8 + r) * 256 + tid] = h2u(p3);
            } else {
                __half2 d = __habs2(__hsub2(u2h(aff[(0*8+r)*256 + tid]), p0));
                d = __hadd2(d, __habs2(__hsub2(u2h(aff[(1*8+r)*256 + tid]), p1)));
                d = __hadd2(d, __habs2(__hsub2(u2h(aff[(2*8+r)*256 + tid]), p2)));
                d = __hadd2(d, __habs2(__hsub2(u2h(aff[(3*8+r)*256 + tid]), p3)));
                const float2 dd = __half22float2(d);
                if (fullabove) {
                    wsum += dd.x + dd.y;
                } else {
                    const int mi = r >> 1;
                    const int i = i0 + wrow * 16 + gi + ((r & 1) << 3);
                    const int j = j0 + wcol * 32 + ((mi >> 1) << 4)
                                + ((mi & 1) << 3) + gj;
                    const float wlo = (j > i) ? 2.0f : ((j == i) ? 1.0f : 0.0f);
                    const float whi = (j + 1 > i) ? 2.0f : ((j + 1 == i) ? 1.0f : 0.0f);
                    wsum += wlo * dd.x + whi * dd.y;
                }
            }
        }
    }

    // ---- reduce: warp shfl -> smem -> single atomic ----
    if (fullabove) wsum *= 2.0f;
    #pragma unroll
    for (int s2 = 16; s2; s2 >>= 1) wsum += __shfl_xor_sync(0xFFFFFFFFu, wsum, s2);
    __syncthreads();
    float* wsums = (float*)smem;
    if (lid == 0) wsums[wid] = wsum;
    __syncthreads();
    if (tid == 0) {
        float tt = 0.0f;
        #pragma unroll
        for (int wq = 0; wq < 8; ++wq) tt += wsums[wq];
        atomicAdd(&g_sum[level], (double)tt);
    }
}

__global__ void finalize_kernel(float* out) {
    const double n0 = 4.0 * 4096.0 * 4096.0;
    const double n1 = 4.0 * 1024.0 * 1024.0;
    out[0] = (float)((g_sum[0] / n0 + g_sum[1] / n1) * 0.5);
}

// ============================================================================
// Launch
// ============================================================================
extern "C" void kernel_launch(void* const* d_in, const int* in_sizes, int n_in,
                              void* d_out, int out_size)
{
    const float* fea1_0 = (const float*)d_in[0];  // (4, 64, 64, 64)
    const float* fea1_1 = (const float*)d_in[1];  // (4, 128, 32, 32)
    const float* fea2_0 = (const float*)d_in[2];
    const float* fea2_1 = (const float*)d_in[3];
    float* out = (float*)d_out;

    // smem: NSTAGES * stage + 32KB aff buffer
    const int smem0 = 3 * 16384 + 32768;    // C=64  -> 80 KB,  2 CTAs/SM
    const int smem1 = 3 * 32768 + 32768;    // C=128 -> 128 KB, 1 CTA/SM (1 wave)
    cudaFuncSetAttribute(gram_loss_mma<64, 3>,
                         cudaFuncAttributeMaxDynamicSharedMemorySize, smem0);
    cudaFuncSetAttribute(gram_loss_mma<128, 3>,
                         cudaFuncAttributeMaxDynamicSharedMemorySize, smem1);

    init_sums_kernel<<<1, 1>>>();

    convert_kernel<64><<<dim3(64, 4, 2), 256>>>(fea1_0, fea2_0, 4096, L0_OFF);
    convert_kernel<128><<<dim3(16, 4, 2), 256>>>(fea1_1, fea2_1, 1024, L1_OFF);

    // triangular grids: T*(T+1)/2 blocks of 64x64
    gram_loss_mma<64, 3><<<64 * 65 / 2, 256, smem0>>>(4096, L0_OFF, 0);   // 2080
    gram_loss_mma<128, 3><<<16 * 17 / 2, 256, smem1>>>(1024, L1_OFF, 1);  // 136

    finalize_kernel<<<1, 1>>>(out);
}